// round 2
// baseline (speedup 1.0000x reference)
#include <cuda_runtime.h>
#include <cstddef>

#define N_NODES 50000
#define N_EDGES 800000

// ---------------- scratch (static device allocations; no cudaMalloc) --------
__device__ float g_edge_attr[(size_t)N_EDGES * 129];   // [E,129]
__device__ float g_hidden   [(size_t)N_EDGES * 258];   // [E,258] (also reused as [E,256] predictor hidden)
__device__ float g_edge_t   [(size_t)N_EDGES * 256];   // [E,128] or [E,256]
__device__ float g_pred_in  [(size_t)N_EDGES * 384];   // [E,384]
__device__ float g_aggr     [(size_t)N_NODES * 256];   // [N,128] or [N,256]
__device__ float g_h1       [(size_t)N_NODES * 256];
__device__ float g_h2       [(size_t)N_NODES * 128];
__device__ int   g_row      [N_EDGES];
__device__ int   g_col      [N_EDGES];
__device__ int   g_idx_is64;

// ---------------- index dtype sniff + convert -------------------------------
// Reference declares edge_index int64 but JAX w/o x64 emits int32. Detect on
// device: interpret as int64; random indices in [0,50000) interpreted as a
// packed int32 pair give huge values, so 256 consecutive in-range int64 reads
// ~uniquely identify a true int64 buffer.
__global__ void detect_idx_kernel(const void* p) {
    if (blockIdx.x == 0 && threadIdx.x == 0) {
        const long long* q = (const long long*)p;
        int ok = 1;
        for (int i = 0; i < 256; i++) {
            long long v = q[i];
            if (v < 0 || v >= N_NODES) { ok = 0; break; }
        }
        g_idx_is64 = ok;
    }
}

__global__ void convert_idx_kernel(const void* p) {
    int i = blockIdx.x * blockDim.x + threadIdx.x;
    if (i >= 2 * N_EDGES) return;
    long long v;
    if (g_idx_is64) v = ((const long long*)p)[i];
    else            v = (long long)((const int*)p)[i];
    if (i < N_EDGES) g_row[i] = (int)v;
    else             g_col[i - N_EDGES] = (int)v;
}

// ---------------- edge_attr = concat(trust, eq) -----------------------------
__global__ void build_edge_attr_kernel(const float* __restrict__ trust,
                                       const float* __restrict__ eq,
                                       float* __restrict__ ea) {
    long long idx = (long long)blockIdx.x * blockDim.x + threadIdx.x;
    long long total = (long long)N_EDGES * 129;
    if (idx >= total) return;
    int e = (int)(idx / 129);
    int k = (int)(idx % 129);
    ea[idx] = (k == 0) ? trust[e] : eq[(size_t)e * 128 + (k - 1)];
}

// ---------------- zero kernel ------------------------------------------------
__global__ void zero_kernel(float* __restrict__ p, size_t n) {
    size_t i = (size_t)blockIdx.x * blockDim.x + threadIdx.x;
    if (i < n) p[i] = 0.f;
}

// ---------------- tiled fp32 GEMM: C = act(A[M,K] @ B[K,N] + bias) ----------
__global__ __launch_bounds__(256)
void sgemm_bias_act(int M, int N, int K,
                    const float* __restrict__ A, const float* __restrict__ B,
                    const float* __restrict__ bias, float* __restrict__ C,
                    int act) {
    constexpr int BM = 128, BN = 128, BK = 8, TM = 8, TN = 8;
    __shared__ float As[BK][BM + 4];   // +4 pad: conflict-free transposed stores
    __shared__ float Bs[BK][BN];

    const int tid = threadIdx.x;
    const int tx = tid % (BN / TN);    // 0..15
    const int ty = tid / (BN / TN);    // 0..15
    const int mBase = blockIdx.y * BM;
    const int nBase = blockIdx.x * BN;

    float acc[TM][TN];
#pragma unroll
    for (int i = 0; i < TM; i++)
#pragma unroll
        for (int j = 0; j < TN; j++) acc[i][j] = 0.f;

    for (int k0 = 0; k0 < K; k0 += BK) {
        // load A tile (transposed into smem): 8 consecutive threads read one row
#pragma unroll
        for (int i = tid; i < BM * BK; i += 256) {
            int r = i / BK, c = i % BK;
            int gr = mBase + r, gc = k0 + c;
            As[c][r] = (gr < M && gc < K) ? A[(size_t)gr * K + gc] : 0.f;
        }
        // load B tile: coalesced rows
#pragma unroll
        for (int i = tid; i < BK * BN; i += 256) {
            int r = i / BN, c = i % BN;
            int gr = k0 + r, gc = nBase + c;
            Bs[r][c] = (gr < K && gc < N) ? B[(size_t)gr * N + gc] : 0.f;
        }
        __syncthreads();
#pragma unroll
        for (int kk = 0; kk < BK; kk++) {
            float ra[TM], rb[TN];
#pragma unroll
            for (int i = 0; i < TM; i++) ra[i] = As[kk][ty * TM + i];
#pragma unroll
            for (int j = 0; j < TN; j++) rb[j] = Bs[kk][tx * TN + j];
#pragma unroll
            for (int i = 0; i < TM; i++)
#pragma unroll
                for (int j = 0; j < TN; j++)
                    acc[i][j] = fmaf(ra[i], rb[j], acc[i][j]);
        }
        __syncthreads();
    }

#pragma unroll
    for (int i = 0; i < TM; i++) {
        int gr = mBase + ty * TM + i;
        if (gr >= M) continue;
#pragma unroll
        for (int j = 0; j < TN; j++) {
            int gc = nBase + tx * TN + j;
            if (gc >= N) continue;
            float v = acc[i][j] + bias[gc];
            if (act) v = fmaxf(v, 0.f);
            C[(size_t)gr * N + gc] = v;
        }
    }
}

// ---------------- scatter: aggr[col[e]] += xsrc[row[e]] + edge_t[e] ---------
__global__ void scatter_add_kernel(const float* __restrict__ xsrc,
                                   const float* __restrict__ et,
                                   float* __restrict__ aggr, int F4) {
    long long idx = (long long)blockIdx.x * blockDim.x + threadIdx.x;
    long long total = (long long)N_EDGES * F4;
    if (idx >= total) return;
    int e = (int)(idx / F4);
    int f = (int)(idx % F4) * 4;
    int F = F4 * 4;
    int r = g_row[e], c = g_col[e];
    float4 xv = *reinterpret_cast<const float4*>(xsrc + (size_t)r * F + f);
    float4 ev = *reinterpret_cast<const float4*>(et + (size_t)e * F + f);
    float* dst = aggr + (size_t)c * F + f;
    atomicAdd(dst + 0, xv.x + ev.x);
    atomicAdd(dst + 1, xv.y + ev.y);
    atomicAdd(dst + 2, xv.z + ev.z);
    atomicAdd(dst + 3, xv.w + ev.w);
}

// ---------------- gather pred_in = [h2[row], h2[col], eq] -------------------
__global__ void gather_pred_kernel(const float* __restrict__ h2,
                                   const float* __restrict__ eq,
                                   float* __restrict__ pred) {
    long long idx = (long long)blockIdx.x * blockDim.x + threadIdx.x;
    long long total = (long long)N_EDGES * 96;   // 384/4 float4 chunks
    if (idx >= total) return;
    int e  = (int)(idx / 96);
    int cf = (int)(idx % 96);
    float4 v;
    if (cf < 32)
        v = *reinterpret_cast<const float4*>(h2 + (size_t)g_row[e] * 128 + cf * 4);
    else if (cf < 64)
        v = *reinterpret_cast<const float4*>(h2 + (size_t)g_col[e] * 128 + (cf - 32) * 4);
    else
        v = *reinterpret_cast<const float4*>(eq + (size_t)e * 128 + (cf - 64) * 4);
    *reinterpret_cast<float4*>(pred + (size_t)e * 384 + cf * 4) = v;
}

// ---------------- final: out[e] = sigmoid(hp[e] . Wp2 + bp2) ----------------
__global__ void final_kernel(const float* __restrict__ hp,
                             const float* __restrict__ Wp2,
                             const float* __restrict__ bp2,
                             float* __restrict__ out) {
    int warp = (blockIdx.x * blockDim.x + threadIdx.x) >> 5;
    int lane = threadIdx.x & 31;
    if (warp >= N_EDGES) return;
    const float* rowp = hp + (size_t)warp * 256;
    float s = 0.f;
#pragma unroll
    for (int i = lane; i < 256; i += 32) s = fmaf(rowp[i], Wp2[i], s);
#pragma unroll
    for (int o = 16; o; o >>= 1) s += __shfl_xor_sync(0xffffffffu, s, o);
    if (lane == 0) out[warp] = 1.f / (1.f + expf(-(s + bp2[0])));
}

// ---------------- launch -----------------------------------------------------
static inline void launch_gemm(int M, int N, int K, const float* A,
                               const float* B, const float* bias, float* C,
                               int act) {
    dim3 grid((N + 127) / 128, (M + 127) / 128);
    sgemm_bias_act<<<grid, 256>>>(M, N, K, A, B, bias, C, act);
}

extern "C" void kernel_launch(void* const* d_in, const int* in_sizes, int n_in,
                              void* d_out, int out_size) {
    const float* x     = (const float*)d_in[0];
    const void*  eidx  = d_in[1];
    const float* trust = (const float*)d_in[2];
    const float* eq    = (const float*)d_in[3];
    const float* Wm1_1 = (const float*)d_in[4];
    const float* bm1_1 = (const float*)d_in[5];
    const float* Wm2_1 = (const float*)d_in[6];
    const float* bm2_1 = (const float*)d_in[7];
    const float* Wl_1  = (const float*)d_in[8];
    const float* bl_1  = (const float*)d_in[9];
    const float* Wm1_2 = (const float*)d_in[10];
    const float* bm1_2 = (const float*)d_in[11];
    const float* Wm2_2 = (const float*)d_in[12];
    const float* bm2_2 = (const float*)d_in[13];
    const float* Wl_2  = (const float*)d_in[14];
    const float* bl_2  = (const float*)d_in[15];
    const float* Wp1   = (const float*)d_in[16];
    const float* bp1   = (const float*)d_in[17];
    const float* Wp2   = (const float*)d_in[18];
    const float* bp2   = (const float*)d_in[19];
    float* out = (float*)d_out;

    float *ea, *hid, *et, *pin, *aggr, *h1, *h2;
    cudaGetSymbolAddress((void**)&ea,   g_edge_attr);
    cudaGetSymbolAddress((void**)&hid,  g_hidden);
    cudaGetSymbolAddress((void**)&et,   g_edge_t);
    cudaGetSymbolAddress((void**)&pin,  g_pred_in);
    cudaGetSymbolAddress((void**)&aggr, g_aggr);
    cudaGetSymbolAddress((void**)&h1,   g_h1);
    cudaGetSymbolAddress((void**)&h2,   g_h2);

    // indices
    detect_idx_kernel<<<1, 32>>>(eidx);
    convert_idx_kernel<<<(2 * N_EDGES + 255) / 256, 256>>>(eidx);

    // edge_attr
    {
        long long tot = (long long)N_EDGES * 129;
        build_edge_attr_kernel<<<(unsigned)((tot + 255) / 256), 256>>>(trust, eq, ea);
    }

    // ---- layer 1 ----
    launch_gemm(N_EDGES, 258, 129, ea, Wm1_1, bm1_1, hid, 1);     // hidden1
    launch_gemm(N_EDGES, 128, 258, hid, Wm2_1, bm2_1, et, 0);     // edge_t1
    {
        size_t n = (size_t)N_NODES * 128;
        zero_kernel<<<(unsigned)((n + 255) / 256), 256>>>(aggr, n);
    }
    {
        long long tot = (long long)N_EDGES * 32;                   // F4 = 128/4
        scatter_add_kernel<<<(unsigned)((tot + 255) / 256), 256>>>(x, et, aggr, 32);
    }
    launch_gemm(N_NODES, 256, 128, aggr, Wl_1, bl_1, h1, 1);       // h1

    // ---- layer 2 ----
    launch_gemm(N_EDGES, 258, 129, ea, Wm1_2, bm1_2, hid, 1);      // hidden2
    launch_gemm(N_EDGES, 256, 258, hid, Wm2_2, bm2_2, et, 0);      // edge_t2
    {
        size_t n = (size_t)N_NODES * 256;
        zero_kernel<<<(unsigned)((n + 255) / 256), 256>>>(aggr, n);
    }
    {
        long long tot = (long long)N_EDGES * 64;                   // F4 = 256/4
        scatter_add_kernel<<<(unsigned)((tot + 255) / 256), 256>>>(h1, et, aggr, 64);
    }
    launch_gemm(N_NODES, 128, 256, aggr, Wl_2, bl_2, h2, 1);       // h2

    // ---- predictor ----
    {
        long long tot = (long long)N_EDGES * 96;
        gather_pred_kernel<<<(unsigned)((tot + 255) / 256), 256>>>(h2, eq, pin);
    }
    launch_gemm(N_EDGES, 256, 384, pin, Wp1, bp1, hid, 1);         // predictor hidden
    {
        long long threads = (long long)N_EDGES * 32;
        final_kernel<<<(unsigned)((threads + 255) / 256), 256>>>(hid, Wp2, bp2, out);
    }
}

// round 4
// speedup vs baseline: 2.7389x; 2.7389x over previous
#include <cuda_runtime.h>
#include <cuda_bf16.h>
#include <cstdint>
#include <cstddef>

#define N_NODES 50000
#define N_EDGES 800000

// ===================== scratch (static device arrays) =======================
__device__ float g_edge_attr[(size_t)N_EDGES * 160];   // [E,160] (129 real, zero-pad)
__device__ float g_hidden   [(size_t)N_EDGES * 288];   // [E,288] (258 real, zero-pad); reused [E,256]
__device__ float g_edge_t   [(size_t)N_EDGES * 256];
__device__ float g_pred_in  [(size_t)N_EDGES * 384];
__device__ float g_aggr     [(size_t)N_NODES * 256];
__device__ float g_h1       [(size_t)N_NODES * 256];
__device__ float g_h2       [(size_t)N_NODES * 128];
__device__ int   g_row      [N_EDGES];
__device__ int   g_col      [N_EDGES];
__device__ int   g_idx_is64;

// pre-split weights: bf16, K-major [Npad rows][Kpad cols], N padded to 128-mult
#define WT_TOTAL 397312
__device__ __align__(16) __nv_bfloat16 g_wt_hi[WT_TOTAL];
__device__ __align__(16) __nv_bfloat16 g_wt_lo[WT_TOTAL];
#define OFF_Wm1_1 0        // 384 x 160
#define OFF_Wm2_1 61440    // 128 x 288
#define OFF_Wl_1  98304    // 256 x 128
#define OFF_Wm1_2 131072   // 384 x 160
#define OFF_Wm2_2 192512   // 256 x 288
#define OFF_Wl_2  266240   // 128 x 256
#define OFF_Wp1   299008   // 256 x 384

// ===================== index sniff / convert ================================
__global__ void detect_idx_kernel(const void* p) {
    if (blockIdx.x == 0 && threadIdx.x == 0) {
        const long long* q = (const long long*)p;
        int ok = 1;
        for (int i = 0; i < 256; i++) {
            long long v = q[i];
            if (v < 0 || v >= N_NODES) { ok = 0; break; }
        }
        g_idx_is64 = ok;
    }
}
__global__ void convert_idx_kernel(const void* p) {
    int i = blockIdx.x * blockDim.x + threadIdx.x;
    if (i >= 2 * N_EDGES) return;
    long long v;
    if (g_idx_is64) v = ((const long long*)p)[i];
    else            v = (long long)((const int*)p)[i];
    if (i < N_EDGES) g_row[i] = (int)v;
    else             g_col[i - N_EDGES] = (int)v;
}

// ===================== edge_attr build (padded to 160) ======================
__global__ void build_edge_attr_kernel(const float* __restrict__ trust,
                                       const float* __restrict__ eq,
                                       float* __restrict__ ea) {
    long long idx = (long long)blockIdx.x * blockDim.x + threadIdx.x;
    long long total = (long long)N_EDGES * 160;
    if (idx >= total) return;
    int e = (int)(idx / 160);
    int k = (int)(idx % 160);
    float v = 0.f;
    if (k == 0)       v = trust[e];
    else if (k < 129) v = eq[(size_t)e * 128 + (k - 1)];
    ea[idx] = v;
}

__global__ void zero_kernel(float* __restrict__ p, size_t n) {
    size_t i = (size_t)blockIdx.x * blockDim.x + threadIdx.x;
    if (i < n) p[i] = 0.f;
}

// ===================== weight split: W[K,N] -> Wt_hi/lo[Npad,Kpad] ==========
__global__ void split_weight_kernel(const float* __restrict__ W, int K, int N,
                                    int Kpad, int Npad,
                                    __nv_bfloat16* __restrict__ oh,
                                    __nv_bfloat16* __restrict__ ol) {
    int idx = blockIdx.x * blockDim.x + threadIdx.x;
    if (idx >= Npad * Kpad) return;
    int n = idx / Kpad, k = idx % Kpad;
    float v = (k < K && n < N) ? W[(size_t)k * N + n] : 0.f;
    __nv_bfloat16 hi = __float2bfloat16_rn(v);
    float lo = v - __bfloat162float(hi);
    oh[idx] = hi;
    ol[idx] = __float2bfloat16_rn(lo);
}

// ===================== bf16x3 mma.sync GEMM =================================
// C[M,<=Nstore] = act(A[M,K] @ W + bias). W pre-split K-major. K mult of 32.
// Block 128x128 (8 warps, 2x4), warp 64x32, BK=32.
__device__ __forceinline__ void mma16816(float* c, const uint32_t* a,
                                         const uint32_t* b) {
    asm volatile(
        "mma.sync.aligned.m16n8k16.row.col.f32.bf16.bf16.f32 "
        "{%0,%1,%2,%3}, {%4,%5,%6,%7}, {%8,%9}, {%0,%1,%2,%3};"
        : "+f"(c[0]), "+f"(c[1]), "+f"(c[2]), "+f"(c[3])
        : "r"(a[0]), "r"(a[1]), "r"(a[2]), "r"(a[3]), "r"(b[0]), "r"(b[1]));
}

__global__ __launch_bounds__(256, 2)
void gemm_mma(int M, int Nstore, int Nreal, int K,
              const float* __restrict__ A,
              const __nv_bfloat16* __restrict__ Wth,
              const __nv_bfloat16* __restrict__ Wtl,
              const float* __restrict__ bias,
              float* __restrict__ C, int act) {
    // rows padded to 20 words (40 bf16) -> conflict-free fragment LDS
    __shared__ uint32_t As_hi[128 * 20], As_lo[128 * 20];
    __shared__ uint32_t Bs_hi[128 * 20], Bs_lo[128 * 20];

    const int tid = threadIdx.x;
    const int wid = tid >> 5, lane = tid & 31;
    const int warpM = (wid >> 2) * 64;      // 0 or 64
    const int warpN = (wid & 3) * 32;       // 0..96
    const int g = lane >> 2, q = lane & 3;
    const long long mBase = (long long)blockIdx.y * 128;
    const int nBase = blockIdx.x * 128;

    float acc[4][4][4];
#pragma unroll
    for (int i = 0; i < 4; i++)
#pragma unroll
        for (int j = 0; j < 4; j++)
#pragma unroll
            for (int t = 0; t < 4; t++) acc[i][j][t] = 0.f;

    const int nChunks = K >> 5;
    for (int kc = 0; kc < nChunks; kc++) {
        const int k0 = kc * 32;
        __syncthreads();
        // ---- A chunk: fp32 float2 load, hi/lo split, packed b32 STS ----
#pragma unroll
        for (int i = tid; i < 2048; i += 256) {
            int r = i >> 4, kp = i & 15;
            long long gr = mBase + r;
            float v0 = 0.f, v1 = 0.f;
            if (gr < M) {
                float2 v = *reinterpret_cast<const float2*>(
                    A + (size_t)gr * K + k0 + kp * 2);
                v0 = v.x; v1 = v.y;
            }
            __nv_bfloat16 h0 = __float2bfloat16_rn(v0);
            __nv_bfloat16 h1 = __float2bfloat16_rn(v1);
            __nv_bfloat16 l0 = __float2bfloat16_rn(v0 - __bfloat162float(h0));
            __nv_bfloat16 l1 = __float2bfloat16_rn(v1 - __bfloat162float(h1));
            As_hi[r * 20 + kp] = (uint32_t)__bfloat16_as_ushort(h0) |
                                 ((uint32_t)__bfloat16_as_ushort(h1) << 16);
            As_lo[r * 20 + kp] = (uint32_t)__bfloat16_as_ushort(l0) |
                                 ((uint32_t)__bfloat16_as_ushort(l1) << 16);
        }
        // ---- B chunk: pre-split bf16 direct copy ----
#pragma unroll
        for (int i = tid; i < 2048; i += 256) {
            int r = i >> 4, kp = i & 15;
            size_t gi = (size_t)(nBase + r) * K + k0 + kp * 2;
            Bs_hi[r * 20 + kp] = *reinterpret_cast<const uint32_t*>(Wth + gi);
            Bs_lo[r * 20 + kp] = *reinterpret_cast<const uint32_t*>(Wtl + gi);
        }
        __syncthreads();

#pragma unroll
        for (int s = 0; s < 2; s++) {
            uint32_t ah[4][4], al[4][4];
#pragma unroll
            for (int i = 0; i < 4; i++) {
                int base = (warpM + i * 16 + g) * 20 + s * 8 + q;
                ah[i][0] = As_hi[base];       ah[i][1] = As_hi[base + 160];
                ah[i][2] = As_hi[base + 4];   ah[i][3] = As_hi[base + 164];
                al[i][0] = As_lo[base];       al[i][1] = As_lo[base + 160];
                al[i][2] = As_lo[base + 4];   al[i][3] = As_lo[base + 164];
            }
#pragma unroll
            for (int j = 0; j < 4; j++) {
                int bb = (warpN + j * 8 + g) * 20 + s * 8 + q;
                uint32_t bh[2] = { Bs_hi[bb], Bs_hi[bb + 4] };
                uint32_t bl[2] = { Bs_lo[bb], Bs_lo[bb + 4] };
#pragma unroll
                for (int i = 0; i < 4; i++) {
                    mma16816(acc[i][j], ah[i], bh);
                    mma16816(acc[i][j], ah[i], bl);
                    mma16816(acc[i][j], al[i], bh);
                }
            }
        }
    }

    // ---- epilogue: bias + act + coalesced float2 stores ----
#pragma unroll
    for (int i = 0; i < 4; i++) {
        long long r0 = mBase + warpM + i * 16 + g;
#pragma unroll
        for (int j = 0; j < 4; j++) {
            int c0 = nBase + warpN + j * 8 + q * 2;
            if (c0 >= Nstore) continue;
            float b0 = (c0 < Nreal) ? bias[c0] : 0.f;
            float b1 = (c0 + 1 < Nreal) ? bias[c0 + 1] : 0.f;
            if (r0 < M) {
                float v0 = acc[i][j][0] + b0, v1 = acc[i][j][1] + b1;
                if (act) { v0 = fmaxf(v0, 0.f); v1 = fmaxf(v1, 0.f); }
                *reinterpret_cast<float2*>(C + (size_t)r0 * Nstore + c0) =
                    make_float2(v0, v1);
            }
            if (r0 + 8 < M) {
                float v0 = acc[i][j][2] + b0, v1 = acc[i][j][3] + b1;
                if (act) { v0 = fmaxf(v0, 0.f); v1 = fmaxf(v1, 0.f); }
                *reinterpret_cast<float2*>(C + (size_t)(r0 + 8) * Nstore + c0) =
                    make_float2(v0, v1);
            }
        }
    }
}

// ===================== scatter / gather / final =============================
__global__ void scatter_add_kernel(const float* __restrict__ xsrc,
                                   const float* __restrict__ et,
                                   float* __restrict__ aggr, int F4) {
    long long idx = (long long)blockIdx.x * blockDim.x + threadIdx.x;
    long long total = (long long)N_EDGES * F4;
    if (idx >= total) return;
    int e = (int)(idx / F4);
    int f = (int)(idx % F4) * 4;
    int F = F4 * 4;
    int r = g_row[e], c = g_col[e];
    float4 xv = *reinterpret_cast<const float4*>(xsrc + (size_t)r * F + f);
    float4 ev = *reinterpret_cast<const float4*>(et + (size_t)e * F + f);
    float* dst = aggr + (size_t)c * F + f;
    atomicAdd(dst + 0, xv.x + ev.x);
    atomicAdd(dst + 1, xv.y + ev.y);
    atomicAdd(dst + 2, xv.z + ev.z);
    atomicAdd(dst + 3, xv.w + ev.w);
}

__global__ void gather_pred_kernel(const float* __restrict__ h2,
                                   const float* __restrict__ eq,
                                   float* __restrict__ pred) {
    long long idx = (long long)blockIdx.x * blockDim.x + threadIdx.x;
    long long total = (long long)N_EDGES * 96;
    if (idx >= total) return;
    int e  = (int)(idx / 96);
    int cf = (int)(idx % 96);
    float4 v;
    if (cf < 32)
        v = *reinterpret_cast<const float4*>(h2 + (size_t)g_row[e] * 128 + cf * 4);
    else if (cf < 64)
        v = *reinterpret_cast<const float4*>(h2 + (size_t)g_col[e] * 128 + (cf - 32) * 4);
    else
        v = *reinterpret_cast<const float4*>(eq + (size_t)e * 128 + (cf - 64) * 4);
    *reinterpret_cast<float4*>(pred + (size_t)e * 384 + cf * 4) = v;
}

__global__ void final_kernel(const float* __restrict__ hp,
                             const float* __restrict__ Wp2,
                             const float* __restrict__ bp2,
                             float* __restrict__ out) {
    int warp = (blockIdx.x * blockDim.x + threadIdx.x) >> 5;
    int lane = threadIdx.x & 31;
    if (warp >= N_EDGES) return;
    const float* rowp = hp + (size_t)warp * 256;
    float s = 0.f;
#pragma unroll
    for (int i = lane; i < 256; i += 32) s = fmaf(rowp[i], Wp2[i], s);
#pragma unroll
    for (int o = 16; o; o >>= 1) s += __shfl_xor_sync(0xffffffffu, s, o);
    if (lane == 0) out[warp] = 1.f / (1.f + expf(-(s + bp2[0])));
}

// ===================== launch ===============================================
static inline void launch_gemm(int M, int Nstore, int Nreal, int K,
                               const float* A,
                               const __nv_bfloat16* Wth, const __nv_bfloat16* Wtl,
                               const float* bias, float* C, int act) {
    dim3 grid((Nstore + 127) / 128, (M + 127) / 128);
    gemm_mma<<<grid, 256>>>(M, Nstore, Nreal, K, A, Wth, Wtl, bias, C, act);
}

static inline void launch_split(const float* W, int K, int N, int Kpad,
                                int Npad, int off) {
    __nv_bfloat16 *wh, *wl;
    cudaGetSymbolAddress((void**)&wh, g_wt_hi);
    cudaGetSymbolAddress((void**)&wl, g_wt_lo);
    int tot = Npad * Kpad;
    split_weight_kernel<<<(tot + 255) / 256, 256>>>(W, K, N, Kpad, Npad,
                                                    wh + off, wl + off);
}

extern "C" void kernel_launch(void* const* d_in, const int* in_sizes, int n_in,
                              void* d_out, int out_size) {
    const float* x     = (const float*)d_in[0];
    const void*  eidx  = d_in[1];
    const float* trust = (const float*)d_in[2];
    const float* eq    = (const float*)d_in[3];
    const float* Wm1_1 = (const float*)d_in[4];
    const float* bm1_1 = (const float*)d_in[5];
    const float* Wm2_1 = (const float*)d_in[6];
    const float* bm2_1 = (const float*)d_in[7];
    const float* Wl_1  = (const float*)d_in[8];
    const float* bl_1  = (const float*)d_in[9];
    const float* Wm1_2 = (const float*)d_in[10];
    const float* bm1_2 = (const float*)d_in[11];
    const float* Wm2_2 = (const float*)d_in[12];
    const float* bm2_2 = (const float*)d_in[13];
    const float* Wl_2  = (const float*)d_in[14];
    const float* bl_2  = (const float*)d_in[15];
    const float* Wp1   = (const float*)d_in[16];
    const float* bp1   = (const float*)d_in[17];
    const float* Wp2   = (const float*)d_in[18];
    const float* bp2   = (const float*)d_in[19];
    float* out = (float*)d_out;

    float *ea, *hid, *et, *pin, *aggr, *h1, *h2;
    cudaGetSymbolAddress((void**)&ea,   g_edge_attr);
    cudaGetSymbolAddress((void**)&hid,  g_hidden);
    cudaGetSymbolAddress((void**)&et,   g_edge_t);
    cudaGetSymbolAddress((void**)&pin,  g_pred_in);
    cudaGetSymbolAddress((void**)&aggr, g_aggr);
    cudaGetSymbolAddress((void**)&h1,   g_h1);
    cudaGetSymbolAddress((void**)&h2,   g_h2);
    __nv_bfloat16 *wh, *wl;
    cudaGetSymbolAddress((void**)&wh, g_wt_hi);
    cudaGetSymbolAddress((void**)&wl, g_wt_lo);

    // indices + edge_attr + weight splits
    detect_idx_kernel<<<1, 32>>>(eidx);
    convert_idx_kernel<<<(2 * N_EDGES + 255) / 256, 256>>>(eidx);
    {
        long long tot = (long long)N_EDGES * 160;
        build_edge_attr_kernel<<<(unsigned)((tot + 255) / 256), 256>>>(trust, eq, ea);
    }
    launch_split(Wm1_1, 129, 258, 160, 384, OFF_Wm1_1);
    launch_split(Wm2_1, 258, 128, 288, 128, OFF_Wm2_1);
    launch_split(Wl_1,  128, 256, 128, 256, OFF_Wl_1);
    launch_split(Wm1_2, 129, 258, 160, 384, OFF_Wm1_2);
    launch_split(Wm2_2, 258, 256, 288, 256, OFF_Wm2_2);
    launch_split(Wl_2,  256, 128, 256, 128, OFF_Wl_2);
    launch_split(Wp1,   384, 256, 384, 256, OFF_Wp1);

    // ---- layer 1 ----
    launch_gemm(N_EDGES, 288, 258, 160, ea, wh + OFF_Wm1_1, wl + OFF_Wm1_1, bm1_1, hid, 1);
    launch_gemm(N_EDGES, 128, 128, 288, hid, wh + OFF_Wm2_1, wl + OFF_Wm2_1, bm2_1, et, 0);
    {
        size_t n = (size_t)N_NODES * 128;
        zero_kernel<<<(unsigned)((n + 255) / 256), 256>>>(aggr, n);
    }
    {
        long long tot = (long long)N_EDGES * 32;
        scatter_add_kernel<<<(unsigned)((tot + 255) / 256), 256>>>(x, et, aggr, 32);
    }
    launch_gemm(N_NODES, 256, 256, 128, aggr, wh + OFF_Wl_1, wl + OFF_Wl_1, bl_1, h1, 1);

    // ---- layer 2 ----
    launch_gemm(N_EDGES, 288, 258, 160, ea, wh + OFF_Wm1_2, wl + OFF_Wm1_2, bm1_2, hid, 1);
    launch_gemm(N_EDGES, 256, 256, 288, hid, wh + OFF_Wm2_2, wl + OFF_Wm2_2, bm2_2, et, 0);
    {
        size_t n = (size_t)N_NODES * 256;
        zero_kernel<<<(unsigned)((n + 255) / 256), 256>>>(aggr, n);
    }
    {
        long long tot = (long long)N_EDGES * 64;
        scatter_add_kernel<<<(unsigned)((tot + 255) / 256), 256>>>(h1, et, aggr, 64);
    }
    launch_gemm(N_NODES, 128, 128, 256, aggr, wh + OFF_Wl_2, wl + OFF_Wl_2, bl_2, h2, 1);

    // ---- predictor ----
    {
        long long tot = (long long)N_EDGES * 96;
        gather_pred_kernel<<<(unsigned)((tot + 255) / 256), 256>>>(h2, eq, pin);
    }
    launch_gemm(N_EDGES, 256, 256, 384, pin, wh + OFF_Wp1, wl + OFF_Wp1, bp1, hid, 1);
    {
        long long threads = (long long)N_EDGES * 32;
        final_kernel<<<(unsigned)((threads + 255) / 256), 256>>>(hid, Wp2, bp2, out);
    }
}

// round 6
// speedup vs baseline: 3.6629x; 1.3374x over previous
#include <cuda_runtime.h>
#include <cuda_bf16.h>
#include <cstdint>
#include <cstddef>

#define N_NODES 50000
#define N_EDGES 800000

// ===================== scratch ==============================================
__device__ float g_hidden[(size_t)N_EDGES * 288];   // edge-MLP hidden (288 pad)
__device__ float g_aggr  [(size_t)N_NODES * 256];
__device__ float g_h1    [(size_t)N_NODES * 256];
__device__ float g_h2    [(size_t)N_NODES * 128];
__device__ float g_logit [N_EDGES];
__device__ int   g_row[N_EDGES];
__device__ int   g_col[N_EDGES];
__device__ int   g_idx_is64;

// pre-split weights: bf16 K-major [Npad][Kpad], Npad mult of 128
#define WT_TOTAL 397312
__device__ __align__(16) __nv_bfloat16 g_wt_hi[WT_TOTAL];
__device__ __align__(16) __nv_bfloat16 g_wt_lo[WT_TOTAL];
#define OFF_Wm1_1 0        // 384 x 160
#define OFF_Wm2_1 61440    // 128 x 288
#define OFF_Wl_1  98304    // 256 x 128
#define OFF_Wm1_2 131072   // 384 x 160
#define OFF_Wm2_2 192512   // 256 x 288
#define OFF_Wl_2  266240   // 128 x 256
#define OFF_Wp1   299008   // 256 x 384

// ===================== small helpers ========================================
__device__ __forceinline__ uint32_t smem_u32(const void* p) {
    uint32_t a;
    asm("{ .reg .u64 t; cvta.to.shared.u64 t, %1; cvt.u32.u64 %0, t; }"
        : "=r"(a) : "l"(p));
    return a;
}
__device__ __forceinline__ void cp_async16(uint32_t dst, const void* src) {
    asm volatile("cp.async.cg.shared.global [%0], [%1], 16;"
                 :: "r"(dst), "l"(src));
}
__device__ __forceinline__ void cp_async4(uint32_t dst, const void* src) {
    asm volatile("cp.async.ca.shared.global [%0], [%1], 4;"
                 :: "r"(dst), "l"(src));
}
#define CP_COMMIT()  asm volatile("cp.async.commit_group;" ::: "memory")
#define CP_WAIT(n)   asm volatile("cp.async.wait_group %0;" :: "n"(n) : "memory")

__device__ __forceinline__ void mma16816(float* c, const uint32_t* a,
                                         const uint32_t* b) {
    asm volatile(
        "mma.sync.aligned.m16n8k16.row.col.f32.bf16.bf16.f32 "
        "{%0,%1,%2,%3}, {%4,%5,%6,%7}, {%8,%9}, {%0,%1,%2,%3};"
        : "+f"(c[0]), "+f"(c[1]), "+f"(c[2]), "+f"(c[3])
        : "r"(a[0]), "r"(a[1]), "r"(a[2]), "r"(a[3]), "r"(b[0]), "r"(b[1]));
}

// ===================== index sniff / convert ================================
__global__ void detect_idx_kernel(const void* p) {
    if (blockIdx.x == 0 && threadIdx.x == 0) {
        const long long* q = (const long long*)p;
        int ok = 1;
        for (int i = 0; i < 256; i++) {
            long long v = q[i];
            if (v < 0 || v >= N_NODES) { ok = 0; break; }
        }
        g_idx_is64 = ok;
    }
}
__global__ void convert_idx_kernel(const void* p) {
    int i = blockIdx.x * blockDim.x + threadIdx.x;
    if (i >= 2 * N_EDGES) return;
    long long v;
    if (g_idx_is64) v = ((const long long*)p)[i];
    else            v = (long long)((const int*)p)[i];
    if (i < N_EDGES) g_row[i] = (int)v;
    else             g_col[i - N_EDGES] = (int)v;
}

__global__ void zero_kernel(float* __restrict__ p, size_t n) {
    size_t i = (size_t)blockIdx.x * blockDim.x + threadIdx.x;
    if (i < n) p[i] = 0.f;
}

// ===================== weight split =========================================
__global__ void split_weight_kernel(const float* __restrict__ W, int K, int N,
                                    int Kpad, int Npad,
                                    __nv_bfloat16* __restrict__ oh,
                                    __nv_bfloat16* __restrict__ ol) {
    int idx = blockIdx.x * blockDim.x + threadIdx.x;
    if (idx >= Npad * Kpad) return;
    int n = idx / Kpad, k = idx % Kpad;
    float v = (k < K && n < N) ? W[(size_t)k * N + n] : 0.f;
    __nv_bfloat16 hi = __float2bfloat16_rn(v);
    float lo = v - __bfloat162float(hi);
    oh[idx] = hi;
    ol[idx] = __float2bfloat16_rn(lo);
}

// ===================== pipelined bf16x3 mma GEMM ============================
// AMODE: 0 plain fp32 A[M,K]; 1 virtual edge_attr (trust,eq); 2 virtual
//        pred_in (h2[row]|h2[col]|eq).
// EPI:   0 store fp32 (bias+optional relu); 1 scatter-atomic into aggr with
//        xsrc[row[e]] add; 2 relu+dot(Wp2) reduce -> atomicAdd logits.
// Block 128x128, 8 warps (2x4), warp 64x32, BK=32 chunks, cp.async 2-stage.
#define SMEM_BYTES 114688
// layout: rawA fp32 2x[128][32] @0 (32KB); AsH 2x2560 w @32768; AsL @53248;
//         BsH @73728; BsL @94208 (each 2 bufs x 2560 words, row stride 20)

template<int AMODE, int EPI>
__global__ __launch_bounds__(256, 2)
void gemm_pipe(int M, int Nstore, int Nreal, int K, int Kreal,
               const float* __restrict__ A,
               const float* __restrict__ trust,
               const float* __restrict__ eq,
               const float* __restrict__ h2,
               const __nv_bfloat16* __restrict__ Wth,
               const __nv_bfloat16* __restrict__ Wtl,
               const float* __restrict__ bias,
               float* __restrict__ Cout,
               const float* __restrict__ xsrc,
               const float* __restrict__ Wp2,
               int act) {
    extern __shared__ char smem[];
    float*    rawA = reinterpret_cast<float*>(smem);
    uint32_t* AsH  = reinterpret_cast<uint32_t*>(smem + 32768);
    uint32_t* AsL  = reinterpret_cast<uint32_t*>(smem + 53248);
    uint32_t* BsH  = reinterpret_cast<uint32_t*>(smem + 73728);
    uint32_t* BsL  = reinterpret_cast<uint32_t*>(smem + 94208);
    const uint32_t sbRaw = smem_u32(rawA);
    const uint32_t sbBH  = smem_u32(BsH);
    const uint32_t sbBL  = smem_u32(BsL);

    const int tid = threadIdx.x;
    const int wid = tid >> 5, lane = tid & 31;
    const int warpM = (wid >> 2) * 64;
    const int warpN = (wid & 3) * 32;
    const int g = lane >> 2, q = lane & 3;
    const long long mBase = (long long)blockIdx.y * 128;
    const int nBase = blockIdx.x * 128;
    const int nChunks = K >> 5;

    float acc[4][4][4];
#pragma unroll
    for (int i = 0; i < 4; i++)
#pragma unroll
        for (int j = 0; j < 4; j++)
#pragma unroll
            for (int t = 0; t < 4; t++) acc[i][j][t] = 0.f;

    auto issue_chunk = [&](int kc, int buf) {
        const int k0 = kc * 32;
        if (AMODE == 0) {
#pragma unroll
            for (int i = tid; i < 1024; i += 256) {
                int r = i >> 3, c4 = i & 7;
                long long gr = mBase + r;
                if (gr >= M) gr = 0;
                cp_async16(sbRaw + ((buf * 4096 + r * 32 + c4 * 4) << 2),
                           A + (size_t)gr * K + k0 + c4 * 4);
            }
        } else if (AMODE == 1) {
            for (int i = tid; i < 4096; i += 256) {
                int r = i >> 5, c = i & 31;
                int k = k0 + c;
                if (k >= 129) continue;
                long long e = mBase + r;
                const float* src = (k == 0) ? (trust + e)
                                            : (eq + (size_t)e * 128 + (k - 1));
                cp_async4(sbRaw + ((buf * 4096 + r * 32 + c) << 2), src);
            }
        } else {
            const int seg = k0 >> 7, koff = k0 & 127;
#pragma unroll
            for (int i = tid; i < 1024; i += 256) {
                int r = i >> 3, c4 = i & 7;
                long long e = mBase + r;
                const float* src;
                if (seg == 0)
                    src = h2 + (size_t)g_row[e] * 128 + koff + c4 * 4;
                else if (seg == 1)
                    src = h2 + (size_t)g_col[e] * 128 + koff + c4 * 4;
                else
                    src = eq + (size_t)e * 128 + koff + c4 * 4;
                cp_async16(sbRaw + ((buf * 4096 + r * 32 + c4 * 4) << 2), src);
            }
        }
#pragma unroll
        for (int i = tid; i < 1024; i += 256) {
            int r = i >> 3, h = (i >> 2) & 1, c4 = i & 3;
            size_t gi = (size_t)(nBase + r) * K + k0 + c4 * 8;
            uint32_t dst = (h ? sbBL : sbBH) + ((buf * 2560 + r * 20 + c4 * 4) << 2);
            cp_async16(dst, (h ? Wtl : Wth) + gi);
        }
        CP_COMMIT();
    };

    issue_chunk(0, 0);

    for (int kc = 0; kc < nChunks; kc++) {
        const int buf = kc & 1;
        // RACE FIX: all warps must finish the MMA that reads buf^1 before we
        // issue cp.async stores into buf^1 (and before reusing rawA[buf^1]).
        __syncthreads();
        if (kc + 1 < nChunks) { issue_chunk(kc + 1, buf ^ 1); CP_WAIT(1); }
        else                  { CP_WAIT(0); }
        __syncthreads();

        // ---- convert raw fp32 -> split bf16 hi/lo ----
        const int k0 = kc * 32;
#pragma unroll
        for (int i = tid; i < 2048; i += 256) {
            int r = i >> 4, kp = i & 15;
            long long gr = mBase + r;
            int k = k0 + kp * 2;
            float2 v = *reinterpret_cast<float2*>(rawA + buf * 4096 + r * 32 + kp * 2);
            float v0 = (gr < M && k < Kreal)     ? v.x : 0.f;
            float v1 = (gr < M && k + 1 < Kreal) ? v.y : 0.f;
            __nv_bfloat16 h0 = __float2bfloat16_rn(v0);
            __nv_bfloat16 h1 = __float2bfloat16_rn(v1);
            __nv_bfloat16 l0 = __float2bfloat16_rn(v0 - __bfloat162float(h0));
            __nv_bfloat16 l1 = __float2bfloat16_rn(v1 - __bfloat162float(h1));
            AsH[buf * 2560 + r * 20 + kp] =
                (uint32_t)__bfloat16_as_ushort(h0) |
                ((uint32_t)__bfloat16_as_ushort(h1) << 16);
            AsL[buf * 2560 + r * 20 + kp] =
                (uint32_t)__bfloat16_as_ushort(l0) |
                ((uint32_t)__bfloat16_as_ushort(l1) << 16);
        }
        __syncthreads();

        // ---- MMA over this chunk ----
        const int ab = buf * 2560;
#pragma unroll
        for (int s = 0; s < 2; s++) {
            uint32_t ah[4][4], al[4][4];
#pragma unroll
            for (int i = 0; i < 4; i++) {
                int base = ab + (warpM + i * 16 + g) * 20 + s * 8 + q;
                ah[i][0] = AsH[base];       ah[i][1] = AsH[base + 160];
                ah[i][2] = AsH[base + 4];   ah[i][3] = AsH[base + 164];
                al[i][0] = AsL[base];       al[i][1] = AsL[base + 160];
                al[i][2] = AsL[base + 4];   al[i][3] = AsL[base + 164];
            }
#pragma unroll
            for (int j = 0; j < 4; j++) {
                int bb = ab + (warpN + j * 8 + g) * 20 + s * 8 + q;
                uint32_t bh[2] = { BsH[bb], BsH[bb + 4] };
                uint32_t bl[2] = { BsL[bb], BsL[bb + 4] };
#pragma unroll
                for (int i = 0; i < 4; i++) {
                    mma16816(acc[i][j], ah[i], bh);
                    mma16816(acc[i][j], ah[i], bl);
                    mma16816(acc[i][j], al[i], bh);
                }
            }
        }
    }

    // ===================== epilogues =====================
    if (EPI == 0) {
#pragma unroll
        for (int i = 0; i < 4; i++) {
            long long r0 = mBase + warpM + i * 16 + g;
#pragma unroll
            for (int j = 0; j < 4; j++) {
                int c0 = nBase + warpN + j * 8 + q * 2;
                if (c0 >= Nstore) continue;
                float b0 = (c0 < Nreal) ? bias[c0] : 0.f;
                float b1 = (c0 + 1 < Nreal) ? bias[c0 + 1] : 0.f;
                if (r0 < M) {
                    float v0 = acc[i][j][0] + b0, v1 = acc[i][j][1] + b1;
                    if (act) { v0 = fmaxf(v0, 0.f); v1 = fmaxf(v1, 0.f); }
                    *reinterpret_cast<float2*>(Cout + (size_t)r0 * Nstore + c0) =
                        make_float2(v0, v1);
                }
                if (r0 + 8 < M) {
                    float v0 = acc[i][j][2] + b0, v1 = acc[i][j][3] + b1;
                    if (act) { v0 = fmaxf(v0, 0.f); v1 = fmaxf(v1, 0.f); }
                    *reinterpret_cast<float2*>(Cout + (size_t)(r0 + 8) * Nstore + c0) =
                        make_float2(v0, v1);
                }
            }
        }
    } else if (EPI == 1) {
        // msg scatter: aggr[col[e]][c] += acc + bias[c] + xsrc[row[e]][c]
#pragma unroll
        for (int i = 0; i < 4; i++) {
            long long e0 = mBase + warpM + i * 16 + g;
            long long e1 = e0 + 8;
            int ra0 = g_row[e0], ca0 = g_col[e0];
            int ra1 = g_row[e1], ca1 = g_col[e1];
#pragma unroll
            for (int j = 0; j < 4; j++) {
                int c0 = nBase + warpN + j * 8 + q * 2;
                float b0 = bias[c0], b1 = bias[c0 + 1];
                float2 xv0 = *reinterpret_cast<const float2*>(
                    xsrc + (size_t)ra0 * Nstore + c0);
                float2 xv1 = *reinterpret_cast<const float2*>(
                    xsrc + (size_t)ra1 * Nstore + c0);
                atomicAdd(Cout + (size_t)ca0 * Nstore + c0,     acc[i][j][0] + b0 + xv0.x);
                atomicAdd(Cout + (size_t)ca0 * Nstore + c0 + 1, acc[i][j][1] + b1 + xv0.y);
                atomicAdd(Cout + (size_t)ca1 * Nstore + c0,     acc[i][j][2] + b0 + xv1.x);
                atomicAdd(Cout + (size_t)ca1 * Nstore + c0 + 1, acc[i][j][3] + b1 + xv1.y);
            }
        }
    } else {
        // predictor: logit[e] += sum_c relu(acc+bias[c]) * Wp2[c]
#pragma unroll
        for (int i = 0; i < 4; i++) {
            long long r0 = mBase + warpM + i * 16 + g;
            float p0 = 0.f, p1 = 0.f;
#pragma unroll
            for (int j = 0; j < 4; j++) {
                int c0 = nBase + warpN + j * 8 + q * 2;
                float b0 = bias[c0], b1 = bias[c0 + 1];
                float w0 = Wp2[c0], w1 = Wp2[c0 + 1];
                p0 = fmaf(fmaxf(acc[i][j][0] + b0, 0.f), w0, p0);
                p0 = fmaf(fmaxf(acc[i][j][1] + b1, 0.f), w1, p0);
                p1 = fmaf(fmaxf(acc[i][j][2] + b0, 0.f), w0, p1);
                p1 = fmaf(fmaxf(acc[i][j][3] + b1, 0.f), w1, p1);
            }
            p0 += __shfl_xor_sync(0xffffffffu, p0, 1);
            p0 += __shfl_xor_sync(0xffffffffu, p0, 2);
            p1 += __shfl_xor_sync(0xffffffffu, p1, 1);
            p1 += __shfl_xor_sync(0xffffffffu, p1, 2);
            if (q == 0) {
                atomicAdd(Cout + r0, p0);
                atomicAdd(Cout + r0 + 8, p1);
            }
        }
    }
}

// ===================== sigmoid ==============================================
__global__ void sigmoid_kernel(const float* __restrict__ logit,
                               const float* __restrict__ bp2,
                               float* __restrict__ out) {
    int i = blockIdx.x * blockDim.x + threadIdx.x;
    if (i >= N_EDGES) return;
    out[i] = 1.f / (1.f + expf(-(logit[i] + bp2[0])));
}

// ===================== host =================================================
static inline void launch_split(const float* W, int K, int N, int Kpad,
                                int Npad, int off) {
    __nv_bfloat16 *wh, *wl;
    cudaGetSymbolAddress((void**)&wh, g_wt_hi);
    cudaGetSymbolAddress((void**)&wl, g_wt_lo);
    int tot = Npad * Kpad;
    split_weight_kernel<<<(tot + 255) / 256, 256>>>(W, K, N, Kpad, Npad,
                                                    wh + off, wl + off);
}

extern "C" void kernel_launch(void* const* d_in, const int* in_sizes, int n_in,
                              void* d_out, int out_size) {
    const float* x     = (const float*)d_in[0];
    const void*  eidx  = d_in[1];
    const float* trust = (const float*)d_in[2];
    const float* eq    = (const float*)d_in[3];
    const float* Wm1_1 = (const float*)d_in[4];
    const float* bm1_1 = (const float*)d_in[5];
    const float* Wm2_1 = (const float*)d_in[6];
    const float* bm2_1 = (const float*)d_in[7];
    const float* Wl_1  = (const float*)d_in[8];
    const float* bl_1  = (const float*)d_in[9];
    const float* Wm1_2 = (const float*)d_in[10];
    const float* bm1_2 = (const float*)d_in[11];
    const float* Wm2_2 = (const float*)d_in[12];
    const float* bm2_2 = (const float*)d_in[13];
    const float* Wl_2  = (const float*)d_in[14];
    const float* bl_2  = (const float*)d_in[15];
    const float* Wp1   = (const float*)d_in[16];
    const float* bp1   = (const float*)d_in[17];
    const float* Wp2   = (const float*)d_in[18];
    const float* bp2   = (const float*)d_in[19];
    float* out = (float*)d_out;

    float *hid, *aggr, *h1, *h2, *logit;
    cudaGetSymbolAddress((void**)&hid,   g_hidden);
    cudaGetSymbolAddress((void**)&aggr,  g_aggr);
    cudaGetSymbolAddress((void**)&h1,    g_h1);
    cudaGetSymbolAddress((void**)&h2,    g_h2);
    cudaGetSymbolAddress((void**)&logit, g_logit);
    __nv_bfloat16 *wh, *wl;
    cudaGetSymbolAddress((void**)&wh, g_wt_hi);
    cudaGetSymbolAddress((void**)&wl, g_wt_lo);

    cudaFuncSetAttribute(gemm_pipe<0,0>, cudaFuncAttributeMaxDynamicSharedMemorySize, SMEM_BYTES);
    cudaFuncSetAttribute(gemm_pipe<0,1>, cudaFuncAttributeMaxDynamicSharedMemorySize, SMEM_BYTES);
    cudaFuncSetAttribute(gemm_pipe<1,0>, cudaFuncAttributeMaxDynamicSharedMemorySize, SMEM_BYTES);
    cudaFuncSetAttribute(gemm_pipe<2,2>, cudaFuncAttributeMaxDynamicSharedMemorySize, SMEM_BYTES);

    detect_idx_kernel<<<1, 32>>>(eidx);
    convert_idx_kernel<<<(2 * N_EDGES + 255) / 256, 256>>>(eidx);

    launch_split(Wm1_1, 129, 258, 160, 384, OFF_Wm1_1);
    launch_split(Wm2_1, 258, 128, 288, 128, OFF_Wm2_1);
    launch_split(Wl_1,  128, 256, 128, 256, OFF_Wl_1);
    launch_split(Wm1_2, 129, 258, 160, 384, OFF_Wm1_2);
    launch_split(Wm2_2, 258, 256, 288, 256, OFF_Wm2_2);
    launch_split(Wl_2,  256, 128, 256, 128, OFF_Wl_2);
    launch_split(Wp1,   384, 256, 384, 256, OFF_Wp1);

    const int MB_E = N_EDGES / 128;               // 6250
    const int MB_N = (N_NODES + 127) / 128;       // 391

    // ---- layer 1 ----
    gemm_pipe<1,0><<<dim3(3, MB_E), 256, SMEM_BYTES>>>(
        N_EDGES, 288, 258, 160, 129, nullptr, trust, eq, nullptr,
        wh + OFF_Wm1_1, wl + OFF_Wm1_1, bm1_1, hid, nullptr, nullptr, 1);
    zero_kernel<<<(N_NODES * 128 + 255) / 256, 256>>>(aggr, (size_t)N_NODES * 128);
    gemm_pipe<0,1><<<dim3(1, MB_E), 256, SMEM_BYTES>>>(
        N_EDGES, 128, 128, 288, 288, hid, nullptr, nullptr, nullptr,
        wh + OFF_Wm2_1, wl + OFF_Wm2_1, bm2_1, aggr, x, nullptr, 0);
    gemm_pipe<0,0><<<dim3(2, MB_N), 256, SMEM_BYTES>>>(
        N_NODES, 256, 256, 128, 128, aggr, nullptr, nullptr, nullptr,
        wh + OFF_Wl_1, wl + OFF_Wl_1, bl_1, h1, nullptr, nullptr, 1);

    // ---- layer 2 ----
    gemm_pipe<1,0><<<dim3(3, MB_E), 256, SMEM_BYTES>>>(
        N_EDGES, 288, 258, 160, 129, nullptr, trust, eq, nullptr,
        wh + OFF_Wm1_2, wl + OFF_Wm1_2, bm1_2, hid, nullptr, nullptr, 1);
    zero_kernel<<<(N_NODES * 256 + 255) / 256, 256>>>(aggr, (size_t)N_NODES * 256);
    gemm_pipe<0,1><<<dim3(2, MB_E), 256, SMEM_BYTES>>>(
        N_EDGES, 256, 256, 288, 288, hid, nullptr, nullptr, nullptr,
        wh + OFF_Wm2_2, wl + OFF_Wm2_2, bm2_2, aggr, h1, nullptr, 0);
    gemm_pipe<0,0><<<dim3(1, MB_N), 256, SMEM_BYTES>>>(
        N_NODES, 128, 128, 256, 256, aggr, nullptr, nullptr, nullptr,
        wh + OFF_Wl_2, wl + OFF_Wl_2, bl_2, h2, nullptr, nullptr, 1);

    // ---- predictor (fused gather + GEMM + reduce) ----
    zero_kernel<<<(N_EDGES + 255) / 256, 256>>>(logit, (size_t)N_EDGES);
    gemm_pipe<2,2><<<dim3(2, MB_E), 256, SMEM_BYTES>>>(
        N_EDGES, 256, 256, 384, 384, nullptr, nullptr, eq, h2,
        wh + OFF_Wp1, wl + OFF_Wp1, bp1, logit, nullptr, Wp2, 0);
    sigmoid_kernel<<<(N_EDGES + 255) / 256, 256>>>(logit, bp2, out);
}

// round 7
// speedup vs baseline: 4.1539x; 1.1340x over previous
#include <cuda_runtime.h>
#include <cuda_bf16.h>
#include <cstdint>
#include <cstddef>

#define N_NODES 50000
#define N_EDGES 800000

// ===================== scratch ==============================================
// edge_attr pre-split: cols 0..127 = eq, col 128 = trust, 129..159 = 0
__device__ __align__(16) __nv_bfloat16 g_ea_hi [(size_t)N_EDGES * 160];
__device__ __align__(16) __nv_bfloat16 g_ea_lo [(size_t)N_EDGES * 160];
__device__ __align__(16) __nv_bfloat16 g_hid_hi[(size_t)N_EDGES * 288];
__device__ __align__(16) __nv_bfloat16 g_hid_lo[(size_t)N_EDGES * 288];
__device__ __align__(16) __nv_bfloat16 g_h2_hi [(size_t)N_NODES * 128];
__device__ __align__(16) __nv_bfloat16 g_h2_lo [(size_t)N_NODES * 128];
__device__ float g_aggr [(size_t)N_NODES * 256];
__device__ float g_h1   [(size_t)N_NODES * 256];
__device__ float g_logit[N_EDGES];
__device__ int   g_row[N_EDGES];
__device__ int   g_col[N_EDGES];
__device__ int   g_idx_is64;

// pre-split weights: bf16 K-major [Npad][Kpad]
#define WT_TOTAL 397312
__device__ __align__(16) __nv_bfloat16 g_wt_hi[WT_TOTAL];
__device__ __align__(16) __nv_bfloat16 g_wt_lo[WT_TOTAL];
#define OFF_Wm1_1 0        // 384 x 160 (row-permuted: eq rows first, trust last)
#define OFF_Wm2_1 61440    // 128 x 288
#define OFF_Wl_1  98304    // 256 x 128
#define OFF_Wm1_2 131072   // 384 x 160 (row-permuted)
#define OFF_Wm2_2 192512   // 256 x 288
#define OFF_Wl_2  266240   // 128 x 256
#define OFF_Wp1   299008   // 256 x 384

// ===================== small helpers ========================================
__device__ __forceinline__ uint32_t smem_u32(const void* p) {
    uint32_t a;
    asm("{ .reg .u64 t; cvta.to.shared.u64 t, %1; cvt.u32.u64 %0, t; }"
        : "=r"(a) : "l"(p));
    return a;
}
__device__ __forceinline__ void cp_async16(uint32_t dst, const void* src) {
    asm volatile("cp.async.cg.shared.global [%0], [%1], 16;"
                 :: "r"(dst), "l"(src));
}
#define CP_COMMIT()  asm volatile("cp.async.commit_group;" ::: "memory")
#define CP_WAIT(n)   asm volatile("cp.async.wait_group %0;" :: "n"(n) : "memory")

__device__ __forceinline__ void mma16816(float* c, const uint32_t* a,
                                         const uint32_t* b) {
    asm volatile(
        "mma.sync.aligned.m16n8k16.row.col.f32.bf16.bf16.f32 "
        "{%0,%1,%2,%3}, {%4,%5,%6,%7}, {%8,%9}, {%0,%1,%2,%3};"
        : "+f"(c[0]), "+f"(c[1]), "+f"(c[2]), "+f"(c[3])
        : "r"(a[0]), "r"(a[1]), "r"(a[2]), "r"(a[3]), "r"(b[0]), "r"(b[1]));
}
__device__ __forceinline__ uint32_t pack_hi(float v0, float v1,
                                            uint32_t& lo_out) {
    __nv_bfloat16 h0 = __float2bfloat16_rn(v0);
    __nv_bfloat16 h1 = __float2bfloat16_rn(v1);
    __nv_bfloat16 l0 = __float2bfloat16_rn(v0 - __bfloat162float(h0));
    __nv_bfloat16 l1 = __float2bfloat16_rn(v1 - __bfloat162float(h1));
    lo_out = (uint32_t)__bfloat16_as_ushort(l0) |
             ((uint32_t)__bfloat16_as_ushort(l1) << 16);
    return (uint32_t)__bfloat16_as_ushort(h0) |
           ((uint32_t)__bfloat16_as_ushort(h1) << 16);
}

// ===================== index sniff / convert ================================
__global__ void detect_idx_kernel(const void* p) {
    if (blockIdx.x == 0 && threadIdx.x == 0) {
        const long long* q = (const long long*)p;
        int ok = 1;
        for (int i = 0; i < 256; i++) {
            long long v = q[i];
            if (v < 0 || v >= N_NODES) { ok = 0; break; }
        }
        g_idx_is64 = ok;
    }
}
__global__ void convert_idx_kernel(const void* p) {
    int i = blockIdx.x * blockDim.x + threadIdx.x;
    if (i >= 2 * N_EDGES) return;
    long long v;
    if (g_idx_is64) v = ((const long long*)p)[i];
    else            v = (long long)((const int*)p)[i];
    if (i < N_EDGES) g_row[i] = (int)v;
    else             g_col[i - N_EDGES] = (int)v;
}

__global__ void zero_kernel(float* __restrict__ p, size_t n) {
    size_t i = (size_t)blockIdx.x * blockDim.x + threadIdx.x;
    if (i < n) p[i] = 0.f;
}

// ===================== pre-split edge_attr ==================================
__global__ void split_ea_kernel(const float* __restrict__ trust,
                                const float* __restrict__ eq) {
    long long idx = (long long)blockIdx.x * blockDim.x + threadIdx.x;
    if (idx >= (long long)N_EDGES * 40) return;
    int e  = (int)(idx / 40);
    int k4 = (int)(idx % 40);
    float v0 = 0.f, v1 = 0.f, v2 = 0.f, v3 = 0.f;
    if (k4 < 32) {
        float4 t = *reinterpret_cast<const float4*>(eq + (size_t)e * 128 + k4 * 4);
        v0 = t.x; v1 = t.y; v2 = t.z; v3 = t.w;
    } else if (k4 == 32) {
        v0 = trust[e];
    }
    uint32_t l01, l23;
    uint32_t h01 = pack_hi(v0, v1, l01);
    uint32_t h23 = pack_hi(v2, v3, l23);
    size_t o = (size_t)e * 160 + k4 * 4;
    *reinterpret_cast<uint2*>(g_ea_hi + o) = make_uint2(h01, h23);
    *reinterpret_cast<uint2*>(g_ea_lo + o) = make_uint2(l01, l23);
}

// ===================== weight split (optional row-permute) ==================
// perm=0: src row k (k<K). perm=1 (edge-attr order): k<128 -> orig k+1 (eq),
// k==128 -> orig 0 (trust), else 0.
__global__ void split_weight_kernel(const float* __restrict__ W, int K, int N,
                                    int Kpad, int Npad, int perm,
                                    __nv_bfloat16* __restrict__ oh,
                                    __nv_bfloat16* __restrict__ ol) {
    int idx = blockIdx.x * blockDim.x + threadIdx.x;
    if (idx >= Npad * Kpad) return;
    int n = idx / Kpad, k = idx % Kpad;
    int sk;
    if (perm) sk = (k < 128) ? (k + 1) : ((k == 128) ? 0 : -1);
    else      sk = (k < K) ? k : -1;
    float v = (sk >= 0 && sk < K && n < N) ? W[(size_t)sk * N + n] : 0.f;
    __nv_bfloat16 hi = __float2bfloat16_rn(v);
    float lo = v - __bfloat162float(hi);
    oh[idx] = hi;
    ol[idx] = __float2bfloat16_rn(lo);
}

// ===================== pipelined bf16x3 mma GEMM ============================
// AMODE: 0 fp32 A[M,K] (+convert); 3 pre-split bf16 A (Ah/Al, stride strideA);
//        5 gather pred_in from g_h2_* / g_ea_* via g_row/g_col.
// EPI:   0 store fp32 (bias+opt relu); 1 scatter-atomic into aggr adding
//        xsrc[row[e]]; 2 relu+dot(Wp2)->atomicAdd logits; 3 store split bf16
//        hi/lo (bias+relu).
#define SMEM_BYTES 114688
// rawA fp32 2x4096 @0 (AMODE 0 only); AsH @32768; AsL @53248; BsH @73728;
// BsL @94208 (each 2 bufs x 2560 words, row stride 20)

template<int AMODE, int EPI>
__global__ __launch_bounds__(256, 2)
void gemm_pipe(int M, int Nstore, int Nreal, int K, int strideA,
               const float* __restrict__ A,
               const __nv_bfloat16* __restrict__ Ah,
               const __nv_bfloat16* __restrict__ Al,
               const __nv_bfloat16* __restrict__ Wth,
               const __nv_bfloat16* __restrict__ Wtl,
               const float* __restrict__ bias,
               float* __restrict__ Cout,
               __nv_bfloat16* __restrict__ Ch,
               __nv_bfloat16* __restrict__ Cl,
               const float* __restrict__ xsrc,
               const float* __restrict__ Wp2,
               int act) {
    extern __shared__ char smem[];
    float*    rawA = reinterpret_cast<float*>(smem);
    uint32_t* AsH  = reinterpret_cast<uint32_t*>(smem + 32768);
    uint32_t* AsL  = reinterpret_cast<uint32_t*>(smem + 53248);
    uint32_t* BsH  = reinterpret_cast<uint32_t*>(smem + 73728);
    uint32_t* BsL  = reinterpret_cast<uint32_t*>(smem + 94208);
    const uint32_t sbRaw = smem_u32(rawA);
    const uint32_t sbAH  = smem_u32(AsH);
    const uint32_t sbAL  = smem_u32(AsL);
    const uint32_t sbBH  = smem_u32(BsH);
    const uint32_t sbBL  = smem_u32(BsL);

    const int tid = threadIdx.x;
    const int wid = tid >> 5, lane = tid & 31;
    const int warpM = (wid >> 2) * 64;
    const int warpN = (wid & 3) * 32;
    const int g = lane >> 2, q = lane & 3;
    const long long mBase = (long long)blockIdx.y * 128;
    const int nBase = blockIdx.x * 128;
    const int nChunks = K >> 5;

    float acc[4][4][4];
#pragma unroll
    for (int i = 0; i < 4; i++)
#pragma unroll
        for (int j = 0; j < 4; j++)
#pragma unroll
            for (int t = 0; t < 4; t++) acc[i][j][t] = 0.f;

    auto issue_chunk = [&](int kc, int buf) {
        const int k0 = kc * 32;
        if (AMODE == 0) {
#pragma unroll
            for (int i = tid; i < 1024; i += 256) {
                int r = i >> 3, c4 = i & 7;
                long long gr = mBase + r;
                if (gr >= M) gr = 0;
                cp_async16(sbRaw + ((buf * 4096 + r * 32 + c4 * 4) << 2),
                           A + (size_t)gr * K + k0 + c4 * 4);
            }
        } else if (AMODE == 3) {
#pragma unroll
            for (int i = tid; i < 1024; i += 256) {
                int r = i >> 3, h = (i >> 2) & 1, c4 = i & 3;
                size_t gi = (size_t)(mBase + r) * strideA + k0 + c4 * 8;
                uint32_t dst = (h ? sbAL : sbAH) +
                               ((buf * 2560 + r * 20 + c4 * 4) << 2);
                cp_async16(dst, (h ? Al : Ah) + gi);
            }
        } else {   // AMODE 5: gather [h2[row] | h2[col] | ea(eq cols)]
            const int seg = k0 >> 7, koff = k0 & 127;
#pragma unroll
            for (int i = tid; i < 1024; i += 256) {
                int r = i >> 3, h = (i >> 2) & 1, c4 = i & 3;
                long long e = mBase + r;
                const __nv_bfloat16* src;
                if (seg == 0)
                    src = (h ? g_h2_lo : g_h2_hi) +
                          (size_t)g_row[e] * 128 + koff + c4 * 8;
                else if (seg == 1)
                    src = (h ? g_h2_lo : g_h2_hi) +
                          (size_t)g_col[e] * 128 + koff + c4 * 8;
                else
                    src = (h ? g_ea_lo : g_ea_hi) +
                          (size_t)e * 160 + koff + c4 * 8;
                uint32_t dst = (h ? sbAL : sbAH) +
                               ((buf * 2560 + r * 20 + c4 * 4) << 2);
                cp_async16(dst, src);
            }
        }
#pragma unroll
        for (int i = tid; i < 1024; i += 256) {
            int r = i >> 3, h = (i >> 2) & 1, c4 = i & 3;
            size_t gi = (size_t)(nBase + r) * K + k0 + c4 * 8;
            uint32_t dst = (h ? sbBL : sbBH) +
                           ((buf * 2560 + r * 20 + c4 * 4) << 2);
            cp_async16(dst, (h ? Wtl : Wth) + gi);
        }
        CP_COMMIT();
    };

    issue_chunk(0, 0);

    for (int kc = 0; kc < nChunks; kc++) {
        const int buf = kc & 1;
        // all warps must finish MMA reading buf^1 before refilling it
        __syncthreads();
        if (kc + 1 < nChunks) { issue_chunk(kc + 1, buf ^ 1); CP_WAIT(1); }
        else                  { CP_WAIT(0); }
        __syncthreads();

        if (AMODE == 0) {
            // convert raw fp32 -> split bf16 hi/lo
#pragma unroll
            for (int i = tid; i < 2048; i += 256) {
                int r = i >> 4, kp = i & 15;
                long long gr = mBase + r;
                float2 v = *reinterpret_cast<float2*>(
                    rawA + buf * 4096 + r * 32 + kp * 2);
                float v0 = (gr < M) ? v.x : 0.f;
                float v1 = (gr < M) ? v.y : 0.f;
                uint32_t lo;
                uint32_t hi = pack_hi(v0, v1, lo);
                AsH[buf * 2560 + r * 20 + kp] = hi;
                AsL[buf * 2560 + r * 20 + kp] = lo;
            }
            __syncthreads();
        }

        const int ab = buf * 2560;
#pragma unroll
        for (int s = 0; s < 2; s++) {
            uint32_t ah[4][4], al[4][4];
#pragma unroll
            for (int i = 0; i < 4; i++) {
                int base = ab + (warpM + i * 16 + g) * 20 + s * 8 + q;
                ah[i][0] = AsH[base];       ah[i][1] = AsH[base + 160];
                ah[i][2] = AsH[base + 4];   ah[i][3] = AsH[base + 164];
                al[i][0] = AsL[base];       al[i][1] = AsL[base + 160];
                al[i][2] = AsL[base + 4];   al[i][3] = AsL[base + 164];
            }
#pragma unroll
            for (int j = 0; j < 4; j++) {
                int bb = ab + (warpN + j * 8 + g) * 20 + s * 8 + q;
                uint32_t bh[2] = { BsH[bb], BsH[bb + 4] };
                uint32_t bl[2] = { BsL[bb], BsL[bb + 4] };
#pragma unroll
                for (int i = 0; i < 4; i++) {
                    mma16816(acc[i][j], ah[i], bh);
                    mma16816(acc[i][j], ah[i], bl);
                    mma16816(acc[i][j], al[i], bh);
                }
            }
        }
    }

    // ===================== epilogues =====================
    if (EPI == 0) {
#pragma unroll
        for (int i = 0; i < 4; i++) {
            long long r0 = mBase + warpM + i * 16 + g;
#pragma unroll
            for (int j = 0; j < 4; j++) {
                int c0 = nBase + warpN + j * 8 + q * 2;
                if (c0 >= Nstore) continue;
                float b0 = (c0 < Nreal) ? bias[c0] : 0.f;
                float b1 = (c0 + 1 < Nreal) ? bias[c0 + 1] : 0.f;
                if (r0 < M) {
                    float v0 = acc[i][j][0] + b0, v1 = acc[i][j][1] + b1;
                    if (act) { v0 = fmaxf(v0, 0.f); v1 = fmaxf(v1, 0.f); }
                    *reinterpret_cast<float2*>(Cout + (size_t)r0 * Nstore + c0) =
                        make_float2(v0, v1);
                }
                if (r0 + 8 < M) {
                    float v0 = acc[i][j][2] + b0, v1 = acc[i][j][3] + b1;
                    if (act) { v0 = fmaxf(v0, 0.f); v1 = fmaxf(v1, 0.f); }
                    *reinterpret_cast<float2*>(Cout + (size_t)(r0 + 8) * Nstore + c0) =
                        make_float2(v0, v1);
                }
            }
        }
    } else if (EPI == 1) {
#pragma unroll
        for (int i = 0; i < 4; i++) {
            long long e0 = mBase + warpM + i * 16 + g;
            long long e1 = e0 + 8;
            int ra0 = g_row[e0], ca0 = g_col[e0];
            int ra1 = g_row[e1], ca1 = g_col[e1];
#pragma unroll
            for (int j = 0; j < 4; j++) {
                int c0 = nBase + warpN + j * 8 + q * 2;
                float b0 = bias[c0], b1 = bias[c0 + 1];
                float2 xv0 = *reinterpret_cast<const float2*>(
                    xsrc + (size_t)ra0 * Nstore + c0);
                float2 xv1 = *reinterpret_cast<const float2*>(
                    xsrc + (size_t)ra1 * Nstore + c0);
                atomicAdd(Cout + (size_t)ca0 * Nstore + c0,     acc[i][j][0] + b0 + xv0.x);
                atomicAdd(Cout + (size_t)ca0 * Nstore + c0 + 1, acc[i][j][1] + b1 + xv0.y);
                atomicAdd(Cout + (size_t)ca1 * Nstore + c0,     acc[i][j][2] + b0 + xv1.x);
                atomicAdd(Cout + (size_t)ca1 * Nstore + c0 + 1, acc[i][j][3] + b1 + xv1.y);
            }
        }
    } else if (EPI == 2) {
#pragma unroll
        for (int i = 0; i < 4; i++) {
            long long r0 = mBase + warpM + i * 16 + g;
            float p0 = 0.f, p1 = 0.f;
#pragma unroll
            for (int j = 0; j < 4; j++) {
                int c0 = nBase + warpN + j * 8 + q * 2;
                float b0 = bias[c0], b1 = bias[c0 + 1];
                float w0 = Wp2[c0], w1 = Wp2[c0 + 1];
                p0 = fmaf(fmaxf(acc[i][j][0] + b0, 0.f), w0, p0);
                p0 = fmaf(fmaxf(acc[i][j][1] + b1, 0.f), w1, p0);
                p1 = fmaf(fmaxf(acc[i][j][2] + b0, 0.f), w0, p1);
                p1 = fmaf(fmaxf(acc[i][j][3] + b1, 0.f), w1, p1);
            }
            p0 += __shfl_xor_sync(0xffffffffu, p0, 1);
            p0 += __shfl_xor_sync(0xffffffffu, p0, 2);
            p1 += __shfl_xor_sync(0xffffffffu, p1, 1);
            p1 += __shfl_xor_sync(0xffffffffu, p1, 2);
            if (q == 0) {
                atomicAdd(Cout + r0, p0);
                atomicAdd(Cout + r0 + 8, p1);
            }
        }
    } else {
        // EPI 3: store split bf16 hi/lo with bias + relu
#pragma unroll
        for (int i = 0; i < 4; i++) {
            long long r0 = mBase + warpM + i * 16 + g;
#pragma unroll
            for (int j = 0; j < 4; j++) {
                int c0 = nBase + warpN + j * 8 + q * 2;
                if (c0 >= Nstore) continue;
                float b0 = (c0 < Nreal) ? bias[c0] : 0.f;
                float b1 = (c0 + 1 < Nreal) ? bias[c0 + 1] : 0.f;
                if (r0 < M) {
                    float v0 = fmaxf(acc[i][j][0] + b0, 0.f);
                    float v1 = fmaxf(acc[i][j][1] + b1, 0.f);
                    uint32_t lo;
                    uint32_t hi = pack_hi(v0, v1, lo);
                    *reinterpret_cast<uint32_t*>(Ch + (size_t)r0 * Nstore + c0) = hi;
                    *reinterpret_cast<uint32_t*>(Cl + (size_t)r0 * Nstore + c0) = lo;
                }
                if (r0 + 8 < M) {
                    float v0 = fmaxf(acc[i][j][2] + b0, 0.f);
                    float v1 = fmaxf(acc[i][j][3] + b1, 0.f);
                    uint32_t lo;
                    uint32_t hi = pack_hi(v0, v1, lo);
                    *reinterpret_cast<uint32_t*>(Ch + (size_t)(r0 + 8) * Nstore + c0) = hi;
                    *reinterpret_cast<uint32_t*>(Cl + (size_t)(r0 + 8) * Nstore + c0) = lo;
                }
            }
        }
    }
}

// ===================== sigmoid ==============================================
__global__ void sigmoid_kernel(const float* __restrict__ logit,
                               const float* __restrict__ bp2,
                               float* __restrict__ out) {
    int i = blockIdx.x * blockDim.x + threadIdx.x;
    if (i >= N_EDGES) return;
    out[i] = 1.f / (1.f + expf(-(logit[i] + bp2[0])));
}

// ===================== host =================================================
static inline void launch_split(const float* W, int K, int N, int Kpad,
                                int Npad, int perm, int off) {
    __nv_bfloat16 *wh, *wl;
    cudaGetSymbolAddress((void**)&wh, g_wt_hi);
    cudaGetSymbolAddress((void**)&wl, g_wt_lo);
    int tot = Npad * Kpad;
    split_weight_kernel<<<(tot + 255) / 256, 256>>>(W, K, N, Kpad, Npad, perm,
                                                    wh + off, wl + off);
}

extern "C" void kernel_launch(void* const* d_in, const int* in_sizes, int n_in,
                              void* d_out, int out_size) {
    const float* x     = (const float*)d_in[0];
    const void*  eidx  = d_in[1];
    const float* trust = (const float*)d_in[2];
    const float* eq    = (const float*)d_in[3];
    const float* Wm1_1 = (const float*)d_in[4];
    const float* bm1_1 = (const float*)d_in[5];
    const float* Wm2_1 = (const float*)d_in[6];
    const float* bm2_1 = (const float*)d_in[7];
    const float* Wl_1  = (const float*)d_in[8];
    const float* bl_1  = (const float*)d_in[9];
    const float* Wm1_2 = (const float*)d_in[10];
    const float* bm1_2 = (const float*)d_in[11];
    const float* Wm2_2 = (const float*)d_in[12];
    const float* bm2_2 = (const float*)d_in[13];
    const float* Wl_2  = (const float*)d_in[14];
    const float* bl_2  = (const float*)d_in[15];
    const float* Wp1   = (const float*)d_in[16];
    const float* bp1   = (const float*)d_in[17];
    const float* Wp2   = (const float*)d_in[18];
    const float* bp2   = (const float*)d_in[19];
    float* out = (float*)d_out;

    float *aggr, *h1, *logit;
    cudaGetSymbolAddress((void**)&aggr,  g_aggr);
    cudaGetSymbolAddress((void**)&h1,    g_h1);
    cudaGetSymbolAddress((void**)&logit, g_logit);
    __nv_bfloat16 *wh, *wl, *eah, *eal, *hidh, *hidl, *h2h, *h2l;
    cudaGetSymbolAddress((void**)&wh,   g_wt_hi);
    cudaGetSymbolAddress((void**)&wl,   g_wt_lo);
    cudaGetSymbolAddress((void**)&eah,  g_ea_hi);
    cudaGetSymbolAddress((void**)&eal,  g_ea_lo);
    cudaGetSymbolAddress((void**)&hidh, g_hid_hi);
    cudaGetSymbolAddress((void**)&hidl, g_hid_lo);
    cudaGetSymbolAddress((void**)&h2h,  g_h2_hi);
    cudaGetSymbolAddress((void**)&h2l,  g_h2_lo);

    cudaFuncSetAttribute(gemm_pipe<3,3>, cudaFuncAttributeMaxDynamicSharedMemorySize, SMEM_BYTES);
    cudaFuncSetAttribute(gemm_pipe<3,1>, cudaFuncAttributeMaxDynamicSharedMemorySize, SMEM_BYTES);
    cudaFuncSetAttribute(gemm_pipe<0,0>, cudaFuncAttributeMaxDynamicSharedMemorySize, SMEM_BYTES);
    cudaFuncSetAttribute(gemm_pipe<0,3>, cudaFuncAttributeMaxDynamicSharedMemorySize, SMEM_BYTES);
    cudaFuncSetAttribute(gemm_pipe<5,2>, cudaFuncAttributeMaxDynamicSharedMemorySize, SMEM_BYTES);

    detect_idx_kernel<<<1, 32>>>(eidx);
    convert_idx_kernel<<<(2 * N_EDGES + 255) / 256, 256>>>(eidx);
    {
        long long tot = (long long)N_EDGES * 40;
        split_ea_kernel<<<(unsigned)((tot + 255) / 256), 256>>>(trust, eq);
    }

    launch_split(Wm1_1, 129, 258, 160, 384, 1, OFF_Wm1_1);
    launch_split(Wm2_1, 258, 128, 288, 128, 0, OFF_Wm2_1);
    launch_split(Wl_1,  128, 256, 128, 256, 0, OFF_Wl_1);
    launch_split(Wm1_2, 129, 258, 160, 384, 1, OFF_Wm1_2);
    launch_split(Wm2_2, 258, 256, 288, 256, 0, OFF_Wm2_2);
    launch_split(Wl_2,  256, 128, 256, 128, 0, OFF_Wl_2);
    launch_split(Wp1,   384, 256, 384, 256, 0, OFF_Wp1);

    const int MB_E = N_EDGES / 128;               // 6250
    const int MB_N = (N_NODES + 127) / 128;       // 391

    // ---- layer 1 ----
    gemm_pipe<3,3><<<dim3(3, MB_E), 256, SMEM_BYTES>>>(
        N_EDGES, 288, 258, 160, 160, nullptr, eah, eal,
        wh + OFF_Wm1_1, wl + OFF_Wm1_1, bm1_1, nullptr, hidh, hidl,
        nullptr, nullptr, 1);
    zero_kernel<<<(N_NODES * 128 + 255) / 256, 256>>>(aggr, (size_t)N_NODES * 128);
    gemm_pipe<3,1><<<dim3(1, MB_E), 256, SMEM_BYTES>>>(
        N_EDGES, 128, 128, 288, 288, nullptr, hidh, hidl,
        wh + OFF_Wm2_1, wl + OFF_Wm2_1, bm2_1, aggr, nullptr, nullptr,
        x, nullptr, 0);
    gemm_pipe<0,0><<<dim3(2, MB_N), 256, SMEM_BYTES>>>(
        N_NODES, 256, 256, 128, 128, aggr, nullptr, nullptr,
        wh + OFF_Wl_1, wl + OFF_Wl_1, bl_1, h1, nullptr, nullptr,
        nullptr, nullptr, 1);

    // ---- layer 2 ----
    gemm_pipe<3,3><<<dim3(3, MB_E), 256, SMEM_BYTES>>>(
        N_EDGES, 288, 258, 160, 160, nullptr, eah, eal,
        wh + OFF_Wm1_2, wl + OFF_Wm1_2, bm1_2, nullptr, hidh, hidl,
        nullptr, nullptr, 1);
    zero_kernel<<<(N_NODES * 256 + 255) / 256, 256>>>(aggr, (size_t)N_NODES * 256);
    gemm_pipe<3,1><<<dim3(2, MB_E), 256, SMEM_BYTES>>>(
        N_EDGES, 256, 256, 288, 288, nullptr, hidh, hidl,
        wh + OFF_Wm2_2, wl + OFF_Wm2_2, bm2_2, aggr, nullptr, nullptr,
        h1, nullptr, 0);
    gemm_pipe<0,3><<<dim3(1, MB_N), 256, SMEM_BYTES>>>(
        N_NODES, 128, 128, 256, 256, aggr, nullptr, nullptr,
        wh + OFF_Wl_2, wl + OFF_Wl_2, bl_2, nullptr, h2h, h2l,
        nullptr, nullptr, 1);

    // ---- predictor ----
    zero_kernel<<<(N_EDGES + 255) / 256, 256>>>(logit, (size_t)N_EDGES);
    gemm_pipe<5,2><<<dim3(2, MB_E), 256, SMEM_BYTES>>>(
        N_EDGES, 256, 256, 384, 0, nullptr, nullptr, nullptr,
        wh + OFF_Wp1, wl + OFF_Wp1, bp1, logit, nullptr, nullptr,
        nullptr, Wp2, 0);
    sigmoid_kernel<<<(N_EDGES + 255) / 256, 256>>>(logit, bp2, out);
}

// round 8
// speedup vs baseline: 4.5668x; 1.0994x over previous
#include <cuda_runtime.h>
#include <cuda_bf16.h>
#include <cstdint>
#include <cstddef>

#define N_NODES 50000
#define N_EDGES 800000

// ===================== scratch ==============================================
__device__ __align__(16) __nv_bfloat16 g_ea_hi [(size_t)N_EDGES * 128];  // eq split
__device__ __align__(16) __nv_bfloat16 g_ea_lo [(size_t)N_EDGES * 128];
__device__ __align__(16) __nv_bfloat16 g_hid_hi[(size_t)N_EDGES * 256];
__device__ __align__(16) __nv_bfloat16 g_hid_lo[(size_t)N_EDGES * 256];
__device__ __align__(16) __nv_bfloat16 g_h2_hi [(size_t)N_NODES * 128];
__device__ __align__(16) __nv_bfloat16 g_h2_lo [(size_t)N_NODES * 128];
__device__ float g_ex1  [(size_t)N_EDGES * 2];   // hidden cols 256,257 (layer1)
__device__ float g_ex2  [(size_t)N_EDGES * 2];   // (layer2)
__device__ float g_aggr [(size_t)N_NODES * 256];
__device__ float g_h1   [(size_t)N_NODES * 256];
__device__ float g_logit[N_EDGES];
__device__ int   g_row[N_EDGES];
__device__ int   g_col[N_EDGES];
__device__ int   g_idx_is64;

// pre-split weights: bf16 K-major [Npad][Kpad]
#define WT_TOTAL 327680
__device__ __align__(16) __nv_bfloat16 g_wt_hi[WT_TOTAL];
__device__ __align__(16) __nv_bfloat16 g_wt_lo[WT_TOTAL];
#define OFF_Wm1_1 0        // 256 x 128 (eq rows, cols 0..255)
#define OFF_Wm2_1 32768    // 128 x 256 (rows 0..255)
#define OFF_Wl_1  65536    // 256 x 128
#define OFF_Wm1_2 98304    // 256 x 128
#define OFF_Wm2_2 131072   // 256 x 256
#define OFF_Wl_2  196608   // 128 x 256
#define OFF_Wp1   229376   // 256 x 384

// ===================== small helpers ========================================
__device__ __forceinline__ uint32_t smem_u32(const void* p) {
    uint32_t a;
    asm("{ .reg .u64 t; cvta.to.shared.u64 t, %1; cvt.u32.u64 %0, t; }"
        : "=r"(a) : "l"(p));
    return a;
}
__device__ __forceinline__ void cp_async16(uint32_t dst, const void* src) {
    asm volatile("cp.async.cg.shared.global [%0], [%1], 16;"
                 :: "r"(dst), "l"(src));
}
#define CP_COMMIT()  asm volatile("cp.async.commit_group;" ::: "memory")
#define CP_WAIT(n)   asm volatile("cp.async.wait_group %0;" :: "n"(n) : "memory")

__device__ __forceinline__ void mma16816(float* c, const uint32_t* a,
                                         const uint32_t* b) {
    asm volatile(
        "mma.sync.aligned.m16n8k16.row.col.f32.bf16.bf16.f32 "
        "{%0,%1,%2,%3}, {%4,%5,%6,%7}, {%8,%9}, {%0,%1,%2,%3};"
        : "+f"(c[0]), "+f"(c[1]), "+f"(c[2]), "+f"(c[3])
        : "r"(a[0]), "r"(a[1]), "r"(a[2]), "r"(a[3]), "r"(b[0]), "r"(b[1]));
}
__device__ __forceinline__ uint32_t pack_hi(float v0, float v1,
                                            uint32_t& lo_out) {
    __nv_bfloat16 h0 = __float2bfloat16_rn(v0);
    __nv_bfloat16 h1 = __float2bfloat16_rn(v1);
    __nv_bfloat16 l0 = __float2bfloat16_rn(v0 - __bfloat162float(h0));
    __nv_bfloat16 l1 = __float2bfloat16_rn(v1 - __bfloat162float(h1));
    lo_out = (uint32_t)__bfloat16_as_ushort(l0) |
             ((uint32_t)__bfloat16_as_ushort(l1) << 16);
    return (uint32_t)__bfloat16_as_ushort(h0) |
           ((uint32_t)__bfloat16_as_ushort(h1) << 16);
}

// ===================== index sniff / convert ================================
__global__ void detect_idx_kernel(const void* p) {
    if (blockIdx.x == 0 && threadIdx.x == 0) {
        const long long* q = (const long long*)p;
        int ok = 1;
        for (int i = 0; i < 256; i++) {
            long long v = q[i];
            if (v < 0 || v >= N_NODES) { ok = 0; break; }
        }
        g_idx_is64 = ok;
    }
}
__global__ void convert_idx_kernel(const void* p) {
    int i = blockIdx.x * blockDim.x + threadIdx.x;
    if (i >= 2 * N_EDGES) return;
    long long v;
    if (g_idx_is64) v = ((const long long*)p)[i];
    else            v = (long long)((const int*)p)[i];
    if (i < N_EDGES) g_row[i] = (int)v;
    else             g_col[i - N_EDGES] = (int)v;
}

__global__ void zero_kernel(float* __restrict__ p, size_t n) {
    size_t i = (size_t)blockIdx.x * blockDim.x + threadIdx.x;
    if (i < n) p[i] = 0.f;
}

// ===================== pre-split eq (edge_attr minus trust) =================
__global__ void split_ea_kernel(const float* __restrict__ eq) {
    long long idx = (long long)blockIdx.x * blockDim.x + threadIdx.x;
    if (idx >= (long long)N_EDGES * 32) return;
    int e  = (int)(idx / 32);
    int k4 = (int)(idx % 32);
    float4 t = *reinterpret_cast<const float4*>(eq + (size_t)e * 128 + k4 * 4);
    uint32_t l01, l23;
    uint32_t h01 = pack_hi(t.x, t.y, l01);
    uint32_t h23 = pack_hi(t.z, t.w, l23);
    size_t o = (size_t)e * 128 + k4 * 4;
    *reinterpret_cast<uint2*>(g_ea_hi + o) = make_uint2(h01, h23);
    *reinterpret_cast<uint2*>(g_ea_lo + o) = make_uint2(l01, l23);
}

// ===================== hidden extra cols (256,257) both layers, fp32 ========
__global__ void hid_extra_kernel(const float* __restrict__ trust,
                                 const float* __restrict__ eq,
                                 const float* __restrict__ Wm1_1,
                                 const float* __restrict__ bm1_1,
                                 const float* __restrict__ Wm1_2,
                                 const float* __restrict__ bm1_2) {
    int warp = (blockIdx.x * blockDim.x + threadIdx.x) >> 5;
    int lane = threadIdx.x & 31;
    if (warp >= N_EDGES) return;
    const float* eqr = eq + (size_t)warp * 128;
    float sA = 0.f, sB = 0.f, sC = 0.f, sD = 0.f;
#pragma unroll
    for (int j = lane; j < 128; j += 32) {
        float v = eqr[j];
        sA = fmaf(v, Wm1_1[(size_t)(j + 1) * 258 + 256], sA);
        sB = fmaf(v, Wm1_1[(size_t)(j + 1) * 258 + 257], sB);
        sC = fmaf(v, Wm1_2[(size_t)(j + 1) * 258 + 256], sC);
        sD = fmaf(v, Wm1_2[(size_t)(j + 1) * 258 + 257], sD);
    }
#pragma unroll
    for (int o = 16; o; o >>= 1) {
        sA += __shfl_xor_sync(0xffffffffu, sA, o);
        sB += __shfl_xor_sync(0xffffffffu, sB, o);
        sC += __shfl_xor_sync(0xffffffffu, sC, o);
        sD += __shfl_xor_sync(0xffffffffu, sD, o);
    }
    if (lane == 0) {
        float t = trust[warp];
        g_ex1[(size_t)warp * 2 + 0] = fmaxf(sA + t * Wm1_1[256] + bm1_1[256], 0.f);
        g_ex1[(size_t)warp * 2 + 1] = fmaxf(sB + t * Wm1_1[257] + bm1_1[257], 0.f);
        g_ex2[(size_t)warp * 2 + 0] = fmaxf(sC + t * Wm1_2[256] + bm1_2[256], 0.f);
        g_ex2[(size_t)warp * 2 + 1] = fmaxf(sD + t * Wm1_2[257] + bm1_2[257], 0.f);
    }
}

// ===================== weight split =========================================
// perm=0: src row k. perm=1: src row k+1 (eq rows of Wm1). NW = actual row
// stride of W; Npad limits cols taken.
__global__ void split_weight_kernel(const float* __restrict__ W, int K, int NW,
                                    int Kpad, int Npad, int perm,
                                    __nv_bfloat16* __restrict__ oh,
                                    __nv_bfloat16* __restrict__ ol) {
    int idx = blockIdx.x * blockDim.x + threadIdx.x;
    if (idx >= Npad * Kpad) return;
    int n = idx / Kpad, k = idx % Kpad;
    int sk = perm ? (k + 1) : k;
    float v = (sk < K) ? W[(size_t)sk * NW + n] : 0.f;
    __nv_bfloat16 hi = __float2bfloat16_rn(v);
    float lo = v - __bfloat162float(hi);
    oh[idx] = hi;
    ol[idx] = __float2bfloat16_rn(lo);
}

// ===================== pipelined bf16x3 mma GEMM ============================
// AMODE: 0 fp32 A (+convert); 3 pre-split bf16 A; 5 gather pred_in.
// EPI:   0 fp32 store; 1 scatter-atomic (+xsrc[row], +rank2 ex·Wrow);
//        2 relu+dot(Wp2)->logits; 3 split-bf16 store (+rank1 trust·Wrow).
#define SMEM_BYTES 114688

template<int AMODE, int EPI>
__global__ __launch_bounds__(256, 2)
void gemm_pipe(int M, int Nstore, int Nreal, int K, int strideA,
               const float* __restrict__ A,
               const __nv_bfloat16* __restrict__ Ah,
               const __nv_bfloat16* __restrict__ Al,
               const __nv_bfloat16* __restrict__ Wth,
               const __nv_bfloat16* __restrict__ Wtl,
               const float* __restrict__ bias,
               float* __restrict__ Cout,
               __nv_bfloat16* __restrict__ Ch,
               __nv_bfloat16* __restrict__ Cl,
               const float* __restrict__ xsrc,
               const float* __restrict__ Wp2,
               const float* __restrict__ Wrow,
               const float* __restrict__ ex,
               int act) {
    extern __shared__ char smem[];
    float*    rawA = reinterpret_cast<float*>(smem);
    uint32_t* AsH  = reinterpret_cast<uint32_t*>(smem + 32768);
    uint32_t* AsL  = reinterpret_cast<uint32_t*>(smem + 53248);
    uint32_t* BsH  = reinterpret_cast<uint32_t*>(smem + 73728);
    uint32_t* BsL  = reinterpret_cast<uint32_t*>(smem + 94208);
    const uint32_t sbRaw = smem_u32(rawA);
    const uint32_t sbAH  = smem_u32(AsH);
    const uint32_t sbAL  = smem_u32(AsL);
    const uint32_t sbBH  = smem_u32(BsH);
    const uint32_t sbBL  = smem_u32(BsL);

    const int tid = threadIdx.x;
    const int wid = tid >> 5, lane = tid & 31;
    const int warpM = (wid >> 2) * 64;
    const int warpN = (wid & 3) * 32;
    const int g = lane >> 2, q = lane & 3;
    const long long mBase = (long long)blockIdx.y * 128;
    const int nBase = blockIdx.x * 128;
    const int nChunks = K >> 5;

    float acc[4][4][4];
#pragma unroll
    for (int i = 0; i < 4; i++)
#pragma unroll
        for (int j = 0; j < 4; j++)
#pragma unroll
            for (int t = 0; t < 4; t++) acc[i][j][t] = 0.f;

    auto issue_chunk = [&](int kc, int buf) {
        const int k0 = kc * 32;
        if (AMODE == 0) {
#pragma unroll
            for (int i = tid; i < 1024; i += 256) {
                int r = i >> 3, c4 = i & 7;
                long long gr = mBase + r;
                if (gr >= M) gr = 0;
                cp_async16(sbRaw + ((buf * 4096 + r * 32 + c4 * 4) << 2),
                           A + (size_t)gr * K + k0 + c4 * 4);
            }
        } else if (AMODE == 3) {
#pragma unroll
            for (int i = tid; i < 1024; i += 256) {
                int r = i >> 3, h = (i >> 2) & 1, c4 = i & 3;
                size_t gi = (size_t)(mBase + r) * strideA + k0 + c4 * 8;
                uint32_t dst = (h ? sbAL : sbAH) +
                               ((buf * 2560 + r * 20 + c4 * 4) << 2);
                cp_async16(dst, (h ? Al : Ah) + gi);
            }
        } else {   // AMODE 5: gather [h2[row] | h2[col] | eq-split]
            const int seg = k0 >> 7, koff = k0 & 127;
#pragma unroll
            for (int i = tid; i < 1024; i += 256) {
                int r = i >> 3, h = (i >> 2) & 1, c4 = i & 3;
                long long e = mBase + r;
                const __nv_bfloat16* src;
                if (seg == 0)
                    src = (h ? g_h2_lo : g_h2_hi) +
                          (size_t)g_row[e] * 128 + koff + c4 * 8;
                else if (seg == 1)
                    src = (h ? g_h2_lo : g_h2_hi) +
                          (size_t)g_col[e] * 128 + koff + c4 * 8;
                else
                    src = (h ? g_ea_lo : g_ea_hi) +
                          (size_t)e * 128 + koff + c4 * 8;
                uint32_t dst = (h ? sbAL : sbAH) +
                               ((buf * 2560 + r * 20 + c4 * 4) << 2);
                cp_async16(dst, src);
            }
        }
#pragma unroll
        for (int i = tid; i < 1024; i += 256) {
            int r = i >> 3, h = (i >> 2) & 1, c4 = i & 3;
            size_t gi = (size_t)(nBase + r) * K + k0 + c4 * 8;
            uint32_t dst = (h ? sbBL : sbBH) +
                           ((buf * 2560 + r * 20 + c4 * 4) << 2);
            cp_async16(dst, (h ? Wtl : Wth) + gi);
        }
        CP_COMMIT();
    };

    issue_chunk(0, 0);

    for (int kc = 0; kc < nChunks; kc++) {
        const int buf = kc & 1;
        __syncthreads();   // all warps done with buf^1's MMA before refill
        if (kc + 1 < nChunks) { issue_chunk(kc + 1, buf ^ 1); CP_WAIT(1); }
        else                  { CP_WAIT(0); }
        __syncthreads();

        if (AMODE == 0) {
#pragma unroll
            for (int i = tid; i < 2048; i += 256) {
                int r = i >> 4, kp = i & 15;
                long long gr = mBase + r;
                float2 v = *reinterpret_cast<float2*>(
                    rawA + buf * 4096 + r * 32 + kp * 2);
                float v0 = (gr < M) ? v.x : 0.f;
                float v1 = (gr < M) ? v.y : 0.f;
                uint32_t lo;
                uint32_t hi = pack_hi(v0, v1, lo);
                AsH[buf * 2560 + r * 20 + kp] = hi;
                AsL[buf * 2560 + r * 20 + kp] = lo;
            }
            __syncthreads();
        }

        const int ab = buf * 2560;
#pragma unroll
        for (int s = 0; s < 2; s++) {
            uint32_t ah[4][4], al[4][4];
#pragma unroll
            for (int i = 0; i < 4; i++) {
                int base = ab + (warpM + i * 16 + g) * 20 + s * 8 + q;
                ah[i][0] = AsH[base];       ah[i][1] = AsH[base + 160];
                ah[i][2] = AsH[base + 4];   ah[i][3] = AsH[base + 164];
                al[i][0] = AsL[base];       al[i][1] = AsL[base + 160];
                al[i][2] = AsL[base + 4];   al[i][3] = AsL[base + 164];
            }
#pragma unroll
            for (int j = 0; j < 4; j++) {
                int bb = ab + (warpN + j * 8 + g) * 20 + s * 8 + q;
                uint32_t bh[2] = { BsH[bb], BsH[bb + 4] };
                uint32_t bl[2] = { BsL[bb], BsL[bb + 4] };
#pragma unroll
                for (int i = 0; i < 4; i++) {
                    mma16816(acc[i][j], ah[i], bh);
                    mma16816(acc[i][j], ah[i], bl);
                    mma16816(acc[i][j], al[i], bh);
                }
            }
        }
    }

    // ===================== epilogues =====================
    if (EPI == 0) {
#pragma unroll
        for (int i = 0; i < 4; i++) {
            long long r0 = mBase + warpM + i * 16 + g;
#pragma unroll
            for (int j = 0; j < 4; j++) {
                int c0 = nBase + warpN + j * 8 + q * 2;
                if (c0 >= Nstore) continue;
                float b0 = (c0 < Nreal) ? bias[c0] : 0.f;
                float b1 = (c0 + 1 < Nreal) ? bias[c0 + 1] : 0.f;
                if (r0 < M) {
                    float v0 = acc[i][j][0] + b0, v1 = acc[i][j][1] + b1;
                    if (act) { v0 = fmaxf(v0, 0.f); v1 = fmaxf(v1, 0.f); }
                    *reinterpret_cast<float2*>(Cout + (size_t)r0 * Nstore + c0) =
                        make_float2(v0, v1);
                }
                if (r0 + 8 < M) {
                    float v0 = acc[i][j][2] + b0, v1 = acc[i][j][3] + b1;
                    if (act) { v0 = fmaxf(v0, 0.f); v1 = fmaxf(v1, 0.f); }
                    *reinterpret_cast<float2*>(Cout + (size_t)(r0 + 8) * Nstore + c0) =
                        make_float2(v0, v1);
                }
            }
        }
    } else if (EPI == 1) {
        const float* w256 = Wrow + (size_t)256 * Nstore;
        const float* w257 = Wrow + (size_t)257 * Nstore;
#pragma unroll
        for (int i = 0; i < 4; i++) {
            long long e0 = mBase + warpM + i * 16 + g;
            long long e1 = e0 + 8;
            int ra0 = g_row[e0], ca0 = g_col[e0];
            int ra1 = g_row[e1], ca1 = g_col[e1];
            float ea0 = ex[e0 * 2], eb0 = ex[e0 * 2 + 1];
            float ea1 = ex[e1 * 2], eb1 = ex[e1 * 2 + 1];
#pragma unroll
            for (int j = 0; j < 4; j++) {
                int c0 = nBase + warpN + j * 8 + q * 2;
                float b0 = bias[c0], b1 = bias[c0 + 1];
                float wa0 = w256[c0], wa1 = w256[c0 + 1];
                float wb0 = w257[c0], wb1 = w257[c0 + 1];
                float2 xv0 = *reinterpret_cast<const float2*>(
                    xsrc + (size_t)ra0 * Nstore + c0);
                float2 xv1 = *reinterpret_cast<const float2*>(
                    xsrc + (size_t)ra1 * Nstore + c0);
                atomicAdd(Cout + (size_t)ca0 * Nstore + c0,
                          acc[i][j][0] + b0 + xv0.x + ea0 * wa0 + eb0 * wb0);
                atomicAdd(Cout + (size_t)ca0 * Nstore + c0 + 1,
                          acc[i][j][1] + b1 + xv0.y + ea0 * wa1 + eb0 * wb1);
                atomicAdd(Cout + (size_t)ca1 * Nstore + c0,
                          acc[i][j][2] + b0 + xv1.x + ea1 * wa0 + eb1 * wb0);
                atomicAdd(Cout + (size_t)ca1 * Nstore + c0 + 1,
                          acc[i][j][3] + b1 + xv1.y + ea1 * wa1 + eb1 * wb1);
            }
        }
    } else if (EPI == 2) {
#pragma unroll
        for (int i = 0; i < 4; i++) {
            long long r0 = mBase + warpM + i * 16 + g;
            float p0 = 0.f, p1 = 0.f;
#pragma unroll
            for (int j = 0; j < 4; j++) {
                int c0 = nBase + warpN + j * 8 + q * 2;
                float b0 = bias[c0], b1 = bias[c0 + 1];
                float w0 = Wp2[c0], w1 = Wp2[c0 + 1];
                p0 = fmaf(fmaxf(acc[i][j][0] + b0, 0.f), w0, p0);
                p0 = fmaf(fmaxf(acc[i][j][1] + b1, 0.f), w1, p0);
                p1 = fmaf(fmaxf(acc[i][j][2] + b0, 0.f), w0, p1);
                p1 = fmaf(fmaxf(acc[i][j][3] + b1, 0.f), w1, p1);
            }
            p0 += __shfl_xor_sync(0xffffffffu, p0, 1);
            p0 += __shfl_xor_sync(0xffffffffu, p0, 2);
            p1 += __shfl_xor_sync(0xffffffffu, p1, 1);
            p1 += __shfl_xor_sync(0xffffffffu, p1, 2);
            if (q == 0) {
                atomicAdd(Cout + r0, p0);
                atomicAdd(Cout + r0 + 8, p1);
            }
        }
    } else {
        // EPI 3: split bf16 store, bias + optional rank-1 trust term + relu
#pragma unroll
        for (int i = 0; i < 4; i++) {
            long long r0 = mBase + warpM + i * 16 + g;
            float t0 = 0.f, t1 = 0.f;
            if (xsrc) {
                if (r0 < M) t0 = xsrc[r0];
                if (r0 + 8 < M) t1 = xsrc[r0 + 8];
            }
#pragma unroll
            for (int j = 0; j < 4; j++) {
                int c0 = nBase + warpN + j * 8 + q * 2;
                if (c0 >= Nstore) continue;
                float b0 = (c0 < Nreal) ? bias[c0] : 0.f;
                float b1 = (c0 + 1 < Nreal) ? bias[c0 + 1] : 0.f;
                float wr0 = xsrc ? Wrow[c0] : 0.f;
                float wr1 = xsrc ? Wrow[c0 + 1] : 0.f;
                if (r0 < M) {
                    float v0 = fmaxf(acc[i][j][0] + b0 + t0 * wr0, 0.f);
                    float v1 = fmaxf(acc[i][j][1] + b1 + t0 * wr1, 0.f);
                    uint32_t lo;
                    uint32_t hi = pack_hi(v0, v1, lo);
                    *reinterpret_cast<uint32_t*>(Ch + (size_t)r0 * Nstore + c0) = hi;
                    *reinterpret_cast<uint32_t*>(Cl + (size_t)r0 * Nstore + c0) = lo;
                }
                if (r0 + 8 < M) {
                    float v0 = fmaxf(acc[i][j][2] + b0 + t1 * wr0, 0.f);
                    float v1 = fmaxf(acc[i][j][3] + b1 + t1 * wr1, 0.f);
                    uint32_t lo;
                    uint32_t hi = pack_hi(v0, v1, lo);
                    *reinterpret_cast<uint32_t*>(Ch + (size_t)(r0 + 8) * Nstore + c0) = hi;
                    *reinterpret_cast<uint32_t*>(Cl + (size_t)(r0 + 8) * Nstore + c0) = lo;
                }
            }
        }
    }
}

// ===================== sigmoid ==============================================
__global__ void sigmoid_kernel(const float* __restrict__ logit,
                               const float* __restrict__ bp2,
                               float* __restrict__ out) {
    int i = blockIdx.x * blockDim.x + threadIdx.x;
    if (i >= N_EDGES) return;
    out[i] = 1.f / (1.f + expf(-(logit[i] + bp2[0])));
}

// ===================== host =================================================
static inline void launch_split(const float* W, int K, int NW, int Kpad,
                                int Npad, int perm, int off) {
    __nv_bfloat16 *wh, *wl;
    cudaGetSymbolAddress((void**)&wh, g_wt_hi);
    cudaGetSymbolAddress((void**)&wl, g_wt_lo);
    int tot = Npad * Kpad;
    split_weight_kernel<<<(tot + 255) / 256, 256>>>(W, K, NW, Kpad, Npad, perm,
                                                    wh + off, wl + off);
}

extern "C" void kernel_launch(void* const* d_in, const int* in_sizes, int n_in,
                              void* d_out, int out_size) {
    const float* x     = (const float*)d_in[0];
    const void*  eidx  = d_in[1];
    const float* trust = (const float*)d_in[2];
    const float* eq    = (const float*)d_in[3];
    const float* Wm1_1 = (const float*)d_in[4];
    const float* bm1_1 = (const float*)d_in[5];
    const float* Wm2_1 = (const float*)d_in[6];
    const float* bm2_1 = (const float*)d_in[7];
    const float* Wl_1  = (const float*)d_in[8];
    const float* bl_1  = (const float*)d_in[9];
    const float* Wm1_2 = (const float*)d_in[10];
    const float* bm1_2 = (const float*)d_in[11];
    const float* Wm2_2 = (const float*)d_in[12];
    const float* bm2_2 = (const float*)d_in[13];
    const float* Wl_2  = (const float*)d_in[14];
    const float* bl_2  = (const float*)d_in[15];
    const float* Wp1   = (const float*)d_in[16];
    const float* bp1   = (const float*)d_in[17];
    const float* Wp2   = (const float*)d_in[18];
    const float* bp2   = (const float*)d_in[19];
    float* out = (float*)d_out;

    float *aggr, *h1, *logit, *ex1, *ex2;
    cudaGetSymbolAddress((void**)&aggr,  g_aggr);
    cudaGetSymbolAddress((void**)&h1,    g_h1);
    cudaGetSymbolAddress((void**)&logit, g_logit);
    cudaGetSymbolAddress((void**)&ex1,   g_ex1);
    cudaGetSymbolAddress((void**)&ex2,   g_ex2);
    __nv_bfloat16 *wh, *wl, *eah, *eal, *hidh, *hidl, *h2h, *h2l;
    cudaGetSymbolAddress((void**)&wh,   g_wt_hi);
    cudaGetSymbolAddress((void**)&wl,   g_wt_lo);
    cudaGetSymbolAddress((void**)&eah,  g_ea_hi);
    cudaGetSymbolAddress((void**)&eal,  g_ea_lo);
    cudaGetSymbolAddress((void**)&hidh, g_hid_hi);
    cudaGetSymbolAddress((void**)&hidl, g_hid_lo);
    cudaGetSymbolAddress((void**)&h2h,  g_h2_hi);
    cudaGetSymbolAddress((void**)&h2l,  g_h2_lo);

    cudaFuncSetAttribute(gemm_pipe<3,3>, cudaFuncAttributeMaxDynamicSharedMemorySize, SMEM_BYTES);
    cudaFuncSetAttribute(gemm_pipe<3,1>, cudaFuncAttributeMaxDynamicSharedMemorySize, SMEM_BYTES);
    cudaFuncSetAttribute(gemm_pipe<0,0>, cudaFuncAttributeMaxDynamicSharedMemorySize, SMEM_BYTES);
    cudaFuncSetAttribute(gemm_pipe<0,3>, cudaFuncAttributeMaxDynamicSharedMemorySize, SMEM_BYTES);
    cudaFuncSetAttribute(gemm_pipe<5,2>, cudaFuncAttributeMaxDynamicSharedMemorySize, SMEM_BYTES);

    detect_idx_kernel<<<1, 32>>>(eidx);
    convert_idx_kernel<<<(2 * N_EDGES + 255) / 256, 256>>>(eidx);
    {
        long long tot = (long long)N_EDGES * 32;
        split_ea_kernel<<<(unsigned)((tot + 255) / 256), 256>>>(eq);
    }
    hid_extra_kernel<<<(N_EDGES * 32 + 255) / 256, 256>>>(trust, eq,
                                                          Wm1_1, bm1_1,
                                                          Wm1_2, bm1_2);

    launch_split(Wm1_1, 129, 258, 128, 256, 1, OFF_Wm1_1);
    launch_split(Wm2_1, 256, 128, 256, 128, 0, OFF_Wm2_1);
    launch_split(Wl_1,  128, 256, 128, 256, 0, OFF_Wl_1);
    launch_split(Wm1_2, 129, 258, 128, 256, 1, OFF_Wm1_2);
    launch_split(Wm2_2, 256, 256, 256, 256, 0, OFF_Wm2_2);
    launch_split(Wl_2,  256, 128, 256, 128, 0, OFF_Wl_2);
    launch_split(Wp1,   384, 256, 384, 256, 0, OFF_Wp1);

    const int MB_E = N_EDGES / 128;               // 6250
    const int MB_N = (N_NODES + 127) / 128;       // 391

    // ---- layer 1 ----
    gemm_pipe<3,3><<<dim3(2, MB_E), 256, SMEM_BYTES>>>(
        N_EDGES, 256, 256, 128, 128, nullptr, eah, eal,
        wh + OFF_Wm1_1, wl + OFF_Wm1_1, bm1_1, nullptr, hidh, hidl,
        trust, nullptr, Wm1_1, nullptr, 1);
    zero_kernel<<<(N_NODES * 128 + 255) / 256, 256>>>(aggr, (size_t)N_NODES * 128);
    gemm_pipe<3,1><<<dim3(1, MB_E), 256, SMEM_BYTES>>>(
        N_EDGES, 128, 128, 256, 256, nullptr, hidh, hidl,
        wh + OFF_Wm2_1, wl + OFF_Wm2_1, bm2_1, aggr, nullptr, nullptr,
        x, nullptr, Wm2_1, ex1, 0);
    gemm_pipe<0,0><<<dim3(2, MB_N), 256, SMEM_BYTES>>>(
        N_NODES, 256, 256, 128, 128, aggr, nullptr, nullptr,
        wh + OFF_Wl_1, wl + OFF_Wl_1, bl_1, h1, nullptr, nullptr,
        nullptr, nullptr, nullptr, nullptr, 1);

    // ---- layer 2 ----
    gemm_pipe<3,3><<<dim3(2, MB_E), 256, SMEM_BYTES>>>(
        N_EDGES, 256, 256, 128, 128, nullptr, eah, eal,
        wh + OFF_Wm1_2, wl + OFF_Wm1_2, bm1_2, nullptr, hidh, hidl,
        trust, nullptr, Wm1_2, nullptr, 1);
    zero_kernel<<<(N_NODES * 256 + 255) / 256, 256>>>(aggr, (size_t)N_NODES * 256);
    gemm_pipe<3,1><<<dim3(2, MB_E), 256, SMEM_BYTES>>>(
        N_EDGES, 256, 256, 256, 256, nullptr, hidh, hidl,
        wh + OFF_Wm2_2, wl + OFF_Wm2_2, bm2_2, aggr, nullptr, nullptr,
        h1, nullptr, Wm2_2, ex2, 0);
    gemm_pipe<0,3><<<dim3(1, MB_N), 256, SMEM_BYTES>>>(
        N_NODES, 128, 128, 256, 256, aggr, nullptr, nullptr,
        wh + OFF_Wl_2, wl + OFF_Wl_2, bl_2, nullptr, h2h, h2l,
        nullptr, nullptr, nullptr, nullptr, 1);

    // ---- predictor ----
    zero_kernel<<<(N_EDGES + 255) / 256, 256>>>(logit, (size_t)N_EDGES);
    gemm_pipe<5,2><<<dim3(2, MB_E), 256, SMEM_BYTES>>>(
        N_EDGES, 256, 256, 384, 0, nullptr, nullptr, nullptr,
        wh + OFF_Wp1, wl + OFF_Wp1, bp1, logit, nullptr, nullptr,
        nullptr, Wp2, nullptr, nullptr, 0);
    sigmoid_kernel<<<(N_EDGES + 255) / 256, 256>>>(logit, bp2, out);
}

// round 10
// speedup vs baseline: 4.8557x; 1.0633x over previous
#include <cuda_runtime.h>
#include <cuda_bf16.h>
#include <cstdint>
#include <cstddef>

#define N_NODES 50000
#define N_EDGES 800000

// ===================== scratch ==============================================
__device__ __align__(16) __nv_bfloat16 g_ea_hi [(size_t)N_EDGES * 128];  // eq split
__device__ __align__(16) __nv_bfloat16 g_ea_lo [(size_t)N_EDGES * 128];
__device__ __align__(16) __nv_bfloat16 g_hid_hi[(size_t)N_EDGES * 256];
__device__ __align__(16) __nv_bfloat16 g_hid_lo[(size_t)N_EDGES * 256];
__device__ __align__(16) __nv_bfloat16 g_h2_hi [(size_t)N_NODES * 128];
__device__ __align__(16) __nv_bfloat16 g_h2_lo [(size_t)N_NODES * 128];
__device__ float g_ex1  [(size_t)N_EDGES * 2];
__device__ float g_ex2  [(size_t)N_EDGES * 2];
__device__ float g_aggr [(size_t)N_NODES * 256];
__device__ float g_h1   [(size_t)N_NODES * 256];
__device__ float g_logit[N_EDGES];
__device__ int   g_row[N_EDGES];
__device__ int   g_col[N_EDGES];
__device__ int   g_idx_is64;

#define WT_TOTAL 327680
__device__ __align__(16) __nv_bfloat16 g_wt_hi[WT_TOTAL];
__device__ __align__(16) __nv_bfloat16 g_wt_lo[WT_TOTAL];
#define OFF_Wm1_1 0
#define OFF_Wm2_1 32768
#define OFF_Wl_1  65536
#define OFF_Wm1_2 98304
#define OFF_Wm2_2 131072
#define OFF_Wl_2  196608
#define OFF_Wp1   229376

// ===================== small helpers ========================================
__device__ __forceinline__ uint32_t smem_u32(const void* p) {
    uint32_t a;
    asm("{ .reg .u64 t; cvta.to.shared.u64 t, %1; cvt.u32.u64 %0, t; }"
        : "=r"(a) : "l"(p));
    return a;
}
__device__ __forceinline__ void cp_async16(uint32_t dst, const void* src) {
    asm volatile("cp.async.cg.shared.global [%0], [%1], 16;"
                 :: "r"(dst), "l"(src));
}
#define CP_COMMIT()  asm volatile("cp.async.commit_group;" ::: "memory")
#define CP_WAIT(n)   asm volatile("cp.async.wait_group %0;" :: "n"(n) : "memory")

__device__ __forceinline__ void mma16816(float* c, const uint32_t* a,
                                         const uint32_t* b) {
    asm volatile(
        "mma.sync.aligned.m16n8k16.row.col.f32.bf16.bf16.f32 "
        "{%0,%1,%2,%3}, {%4,%5,%6,%7}, {%8,%9}, {%0,%1,%2,%3};"
        : "+f"(c[0]), "+f"(c[1]), "+f"(c[2]), "+f"(c[3])
        : "r"(a[0]), "r"(a[1]), "r"(a[2]), "r"(a[3]), "r"(b[0]), "r"(b[1]));
}
__device__ __forceinline__ uint32_t pack_hi(float v0, float v1,
                                            uint32_t& lo_out) {
    __nv_bfloat16 h0 = __float2bfloat16_rn(v0);
    __nv_bfloat16 h1 = __float2bfloat16_rn(v1);
    __nv_bfloat16 l0 = __float2bfloat16_rn(v0 - __bfloat162float(h0));
    __nv_bfloat16 l1 = __float2bfloat16_rn(v1 - __bfloat162float(h1));
    lo_out = (uint32_t)__bfloat16_as_ushort(l0) |
             ((uint32_t)__bfloat16_as_ushort(l1) << 16);
    return (uint32_t)__bfloat16_as_ushort(h0) |
           ((uint32_t)__bfloat16_as_ushort(h1) << 16);
}
__device__ __forceinline__ float2 unsplit2(uint32_t h, uint32_t l) {
    float a0 = __bfloat162float(__ushort_as_bfloat16((unsigned short)(h & 0xffff))) +
               __bfloat162float(__ushort_as_bfloat16((unsigned short)(l & 0xffff)));
    float a1 = __bfloat162float(__ushort_as_bfloat16((unsigned short)(h >> 16))) +
               __bfloat162float(__ushort_as_bfloat16((unsigned short)(l >> 16)));
    return make_float2(a0, a1);
}

// ===================== index sniff / convert ================================
__global__ void detect_idx_kernel(const void* p) {
    if (blockIdx.x == 0 && threadIdx.x == 0) {
        const long long* q = (const long long*)p;
        int ok = 1;
        for (int i = 0; i < 256; i++) {
            long long v = q[i];
            if (v < 0 || v >= N_NODES) { ok = 0; break; }
        }
        g_idx_is64 = ok;
    }
}
__global__ void convert_idx_kernel(const void* p) {
    int i = blockIdx.x * blockDim.x + threadIdx.x;
    if (i >= 2 * N_EDGES) return;
    long long v;
    if (g_idx_is64) v = ((const long long*)p)[i];
    else            v = (long long)((const int*)p)[i];
    if (i < N_EDGES) g_row[i] = (int)v;
    else             g_col[i - N_EDGES] = (int)v;
}

__global__ void zero_kernel(float* __restrict__ p, size_t n) {
    size_t i = (size_t)blockIdx.x * blockDim.x + threadIdx.x;
    if (i < n) p[i] = 0.f;
}

// ===================== pre-split eq =========================================
__global__ void split_ea_kernel(const float* __restrict__ eq) {
    long long idx = (long long)blockIdx.x * blockDim.x + threadIdx.x;
    if (idx >= (long long)N_EDGES * 32) return;
    int e  = (int)(idx / 32);
    int k4 = (int)(idx % 32);
    float4 t = *reinterpret_cast<const float4*>(eq + (size_t)e * 128 + k4 * 4);
    uint32_t l01, l23;
    uint32_t h01 = pack_hi(t.x, t.y, l01);
    uint32_t h23 = pack_hi(t.z, t.w, l23);
    size_t o = (size_t)e * 128 + k4 * 4;
    *reinterpret_cast<uint2*>(g_ea_hi + o) = make_uint2(h01, h23);
    *reinterpret_cast<uint2*>(g_ea_lo + o) = make_uint2(l01, l23);
}

// ===================== weight split =========================================
__global__ void split_weight_kernel(const float* __restrict__ W, int K, int NW,
                                    int Kpad, int Npad, int perm,
                                    __nv_bfloat16* __restrict__ oh,
                                    __nv_bfloat16* __restrict__ ol) {
    int idx = blockIdx.x * blockDim.x + threadIdx.x;
    if (idx >= Npad * Kpad) return;
    int n = idx / Kpad, k = idx % Kpad;
    int sk = perm ? (k + 1) : k;
    float v = (sk < K) ? W[(size_t)sk * NW + n] : 0.f;
    __nv_bfloat16 hi = __float2bfloat16_rn(v);
    float lo = v - __bfloat162float(hi);
    oh[idx] = hi;
    ol[idx] = __float2bfloat16_rn(lo);
}

// ===================== pipelined bf16x3 mma GEMM ============================
// AMODE: 0 fp32 A (+convert; uses rawA words 0..8191);
//        3 pre-split bf16 A (rawA unused -> EX may stage weights at rawA[0..255]);
//        5 gather pred_in.
// EPI:   0 fp32 store; 1 scatter-atomic (+xsrc[row], +rank2 ex·Wrow);
//        2 relu+dot(Wp2)->logits; 3 split-bf16 store (+rank1 trust·Wrow).
// EX=1 (AMODE 3 only): compute hidden cols 256/257 in fp32 (blockIdx.x==0).
#define SMEM_BYTES 114688

template<int AMODE, int EPI, int EX>
__global__ __launch_bounds__(256, 2)
void gemm_pipe(int M, int Nstore, int Nreal, int K, int strideA,
               const float* __restrict__ A,
               const __nv_bfloat16* __restrict__ Ah,
               const __nv_bfloat16* __restrict__ Al,
               const __nv_bfloat16* __restrict__ Wth,
               const __nv_bfloat16* __restrict__ Wtl,
               const float* __restrict__ bias,
               float* __restrict__ Cout,
               __nv_bfloat16* __restrict__ Ch,
               __nv_bfloat16* __restrict__ Cl,
               const float* __restrict__ xsrc,
               const float* __restrict__ Wp2,
               const float* __restrict__ Wrow,
               float* __restrict__ ex,
               int act) {
    extern __shared__ char smem[];
    float*    rawA = reinterpret_cast<float*>(smem);
    uint32_t* AsH  = reinterpret_cast<uint32_t*>(smem + 32768);
    uint32_t* AsL  = reinterpret_cast<uint32_t*>(smem + 53248);
    uint32_t* BsH  = reinterpret_cast<uint32_t*>(smem + 73728);
    uint32_t* BsL  = reinterpret_cast<uint32_t*>(smem + 94208);
    const uint32_t sbRaw = smem_u32(rawA);
    const uint32_t sbAH  = smem_u32(AsH);
    const uint32_t sbAL  = smem_u32(AsL);
    const uint32_t sbBH  = smem_u32(BsH);
    const uint32_t sbBL  = smem_u32(BsL);

    const int tid = threadIdx.x;
    const int wid = tid >> 5, lane = tid & 31;
    const int warpM = (wid >> 2) * 64;
    const int warpN = (wid & 3) * 32;
    const int g = lane >> 2, q = lane & 3;
    const long long mBase = (long long)blockIdx.y * 128;
    const int nBase = blockIdx.x * 128;
    const int nChunks = K >> 5;

    float acc[4][4][4];
#pragma unroll
    for (int i = 0; i < 4; i++)
#pragma unroll
        for (int j = 0; j < 4; j++)
#pragma unroll
            for (int t = 0; t < 4; t++) acc[i][j][t] = 0.f;

    // EX staging: ONLY legal when AMODE != 0 (rawA otherwise unused).
    float exacc = 0.f;
    const bool doEX = EX && (blockIdx.x == 0);
    if (doEX) {
        rawA[tid] = Wrow[(size_t)((tid >> 1) + 1) * 258 + 256 + (tid & 1)];
    }

    auto issue_chunk = [&](int kc, int buf) {
        const int k0 = kc * 32;
        if (AMODE == 0) {
#pragma unroll
            for (int i = tid; i < 1024; i += 256) {
                int r = i >> 3, c4 = i & 7;
                long long gr = mBase + r;
                if (gr >= M) gr = 0;
                cp_async16(sbRaw + ((buf * 4096 + r * 32 + c4 * 4) << 2),
                           A + (size_t)gr * K + k0 + c4 * 4);
            }
        } else if (AMODE == 3) {
#pragma unroll
            for (int i = tid; i < 1024; i += 256) {
                int r = i >> 3, h = (i >> 2) & 1, c4 = i & 3;
                size_t gi = (size_t)(mBase + r) * strideA + k0 + c4 * 8;
                uint32_t dst = (h ? sbAL : sbAH) +
                               ((buf * 2560 + r * 20 + c4 * 4) << 2);
                cp_async16(dst, (h ? Al : Ah) + gi);
            }
        } else {   // AMODE 5: gather [h2[row] | h2[col] | eq-split]
            const int seg = k0 >> 7, koff = k0 & 127;
#pragma unroll
            for (int i = tid; i < 1024; i += 256) {
                int r = i >> 3, h = (i >> 2) & 1, c4 = i & 3;
                long long e = mBase + r;
                const __nv_bfloat16* src;
                if (seg == 0)
                    src = (h ? g_h2_lo : g_h2_hi) +
                          (size_t)g_row[e] * 128 + koff + c4 * 8;
                else if (seg == 1)
                    src = (h ? g_h2_lo : g_h2_hi) +
                          (size_t)g_col[e] * 128 + koff + c4 * 8;
                else
                    src = (h ? g_ea_lo : g_ea_hi) +
                          (size_t)e * 128 + koff + c4 * 8;
                uint32_t dst = (h ? sbAL : sbAH) +
                               ((buf * 2560 + r * 20 + c4 * 4) << 2);
                cp_async16(dst, src);
            }
        }
#pragma unroll
        for (int i = tid; i < 1024; i += 256) {
            int r = i >> 3, h = (i >> 2) & 1, c4 = i & 3;
            size_t gi = (size_t)(nBase + r) * K + k0 + c4 * 8;
            uint32_t dst = (h ? sbBL : sbBH) +
                           ((buf * 2560 + r * 20 + c4 * 4) << 2);
            cp_async16(dst, (h ? Wtl : Wth) + gi);
        }
        CP_COMMIT();
    };

    issue_chunk(0, 0);

    for (int kc = 0; kc < nChunks; kc++) {
        const int buf = kc & 1;
        __syncthreads();
        if (kc + 1 < nChunks) { issue_chunk(kc + 1, buf ^ 1); CP_WAIT(1); }
        else                  { CP_WAIT(0); }
        __syncthreads();

        if (AMODE == 0) {
#pragma unroll
            for (int i = tid; i < 2048; i += 256) {
                int r = i >> 4, kp = i & 15;
                long long gr = mBase + r;
                float2 v = *reinterpret_cast<float2*>(
                    rawA + buf * 4096 + r * 32 + kp * 2);
                float v0 = (gr < M) ? v.x : 0.f;
                float v1 = (gr < M) ? v.y : 0.f;
                uint32_t lo;
                uint32_t hi = pack_hi(v0, v1, lo);
                AsH[buf * 2560 + r * 20 + kp] = hi;
                AsL[buf * 2560 + r * 20 + kp] = lo;
            }
            __syncthreads();
        }

        const int ab = buf * 2560;

        // EX: fp32 accumulation of hidden cols 256/257 from the A smem tile
        if (doEX) {
            int r = tid >> 1, c = tid & 1;
            int base = ab + r * 20;
#pragma unroll
            for (int kp = 0; kp < 16; kp++) {
                float2 a = unsplit2(AsH[base + kp], AsL[base + kp]);
                int k = kc * 32 + kp * 2;
                exacc = fmaf(a.x, rawA[k * 2 + c], exacc);
                exacc = fmaf(a.y, rawA[(k + 1) * 2 + c], exacc);
            }
        }

#pragma unroll
        for (int s = 0; s < 2; s++) {
            uint32_t ah[4][4], al[4][4];
#pragma unroll
            for (int i = 0; i < 4; i++) {
                int base = ab + (warpM + i * 16 + g) * 20 + s * 8 + q;
                ah[i][0] = AsH[base];       ah[i][1] = AsH[base + 160];
                ah[i][2] = AsH[base + 4];   ah[i][3] = AsH[base + 164];
                al[i][0] = AsL[base];       al[i][1] = AsL[base + 160];
                al[i][2] = AsL[base + 4];   al[i][3] = AsL[base + 164];
            }
#pragma unroll
            for (int j = 0; j < 4; j++) {
                int bb = ab + (warpN + j * 8 + g) * 20 + s * 8 + q;
                uint32_t bh[2] = { BsH[bb], BsH[bb + 4] };
                uint32_t bl[2] = { BsL[bb], BsL[bb + 4] };
#pragma unroll
                for (int i = 0; i < 4; i++) {
                    mma16816(acc[i][j], ah[i], bh);
                    mma16816(acc[i][j], ah[i], bl);
                    mma16816(acc[i][j], al[i], bh);
                }
            }
        }
    }

    if (doEX) {
        int r = tid >> 1, c = tid & 1;
        long long e = mBase + r;
        float t = xsrc[e];
        ex[(size_t)e * 2 + c] =
            fmaxf(exacc + t * Wrow[256 + c] + bias[256 + c], 0.f);
    }

    // ===================== epilogues =====================
    if (EPI == 0) {
#pragma unroll
        for (int i = 0; i < 4; i++) {
            long long r0 = mBase + warpM + i * 16 + g;
#pragma unroll
            for (int j = 0; j < 4; j++) {
                int c0 = nBase + warpN + j * 8 + q * 2;
                if (c0 >= Nstore) continue;
                float b0 = (c0 < Nreal) ? bias[c0] : 0.f;
                float b1 = (c0 + 1 < Nreal) ? bias[c0 + 1] : 0.f;
                if (r0 < M) {
                    float v0 = acc[i][j][0] + b0, v1 = acc[i][j][1] + b1;
                    if (act) { v0 = fmaxf(v0, 0.f); v1 = fmaxf(v1, 0.f); }
                    *reinterpret_cast<float2*>(Cout + (size_t)r0 * Nstore + c0) =
                        make_float2(v0, v1);
                }
                if (r0 + 8 < M) {
                    float v0 = acc[i][j][2] + b0, v1 = acc[i][j][3] + b1;
                    if (act) { v0 = fmaxf(v0, 0.f); v1 = fmaxf(v1, 0.f); }
                    *reinterpret_cast<float2*>(Cout + (size_t)(r0 + 8) * Nstore + c0) =
                        make_float2(v0, v1);
                }
            }
        }
    } else if (EPI == 1) {
        const float* w256 = Wrow + (size_t)256 * Nstore;
        const float* w257 = Wrow + (size_t)257 * Nstore;
#pragma unroll
        for (int i = 0; i < 4; i++) {
            long long e0 = mBase + warpM + i * 16 + g;
            long long e1 = e0 + 8;
            int ra0 = g_row[e0], ca0 = g_col[e0];
            int ra1 = g_row[e1], ca1 = g_col[e1];
            float ea0 = ex[e0 * 2], eb0 = ex[e0 * 2 + 1];
            float ea1 = ex[e1 * 2], eb1 = ex[e1 * 2 + 1];
#pragma unroll
            for (int j = 0; j < 4; j++) {
                int c0 = nBase + warpN + j * 8 + q * 2;
                float b0 = bias[c0], b1 = bias[c0 + 1];
                float wa0 = w256[c0], wa1 = w256[c0 + 1];
                float wb0 = w257[c0], wb1 = w257[c0 + 1];
                float2 xv0 = *reinterpret_cast<const float2*>(
                    xsrc + (size_t)ra0 * Nstore + c0);
                float2 xv1 = *reinterpret_cast<const float2*>(
                    xsrc + (size_t)ra1 * Nstore + c0);
                atomicAdd(Cout + (size_t)ca0 * Nstore + c0,
                          acc[i][j][0] + b0 + xv0.x + ea0 * wa0 + eb0 * wb0);
                atomicAdd(Cout + (size_t)ca0 * Nstore + c0 + 1,
                          acc[i][j][1] + b1 + xv0.y + ea0 * wa1 + eb0 * wb1);
                atomicAdd(Cout + (size_t)ca1 * Nstore + c0,
                          acc[i][j][2] + b0 + xv1.x + ea1 * wa0 + eb1 * wb0);
                atomicAdd(Cout + (size_t)ca1 * Nstore + c0 + 1,
                          acc[i][j][3] + b1 + xv1.y + ea1 * wa1 + eb1 * wb1);
            }
        }
    } else if (EPI == 2) {
#pragma unroll
        for (int i = 0; i < 4; i++) {
            long long r0 = mBase + warpM + i * 16 + g;
            float p0 = 0.f, p1 = 0.f;
#pragma unroll
            for (int j = 0; j < 4; j++) {
                int c0 = nBase + warpN + j * 8 + q * 2;
                float b0 = bias[c0], b1 = bias[c0 + 1];
                float w0 = Wp2[c0], w1 = Wp2[c0 + 1];
                p0 = fmaf(fmaxf(acc[i][j][0] + b0, 0.f), w0, p0);
                p0 = fmaf(fmaxf(acc[i][j][1] + b1, 0.f), w1, p0);
                p1 = fmaf(fmaxf(acc[i][j][2] + b0, 0.f), w0, p1);
                p1 = fmaf(fmaxf(acc[i][j][3] + b1, 0.f), w1, p1);
            }
            p0 += __shfl_xor_sync(0xffffffffu, p0, 1);
            p0 += __shfl_xor_sync(0xffffffffu, p0, 2);
            p1 += __shfl_xor_sync(0xffffffffu, p1, 1);
            p1 += __shfl_xor_sync(0xffffffffu, p1, 2);
            if (q == 0) {
                atomicAdd(Cout + r0, p0);
                atomicAdd(Cout + r0 + 8, p1);
            }
        }
    } else {
        // EPI 3: split bf16 store, bias + rank-1 trust term + relu
#pragma unroll
        for (int i = 0; i < 4; i++) {
            long long r0 = mBase + warpM + i * 16 + g;
            float t0 = 0.f, t1 = 0.f;
            if (xsrc) {
                if (r0 < M) t0 = xsrc[r0];
                if (r0 + 8 < M) t1 = xsrc[r0 + 8];
            }
#pragma unroll
            for (int j = 0; j < 4; j++) {
                int c0 = nBase + warpN + j * 8 + q * 2;
                if (c0 >= Nstore) continue;
                float b0 = (c0 < Nreal) ? bias[c0] : 0.f;
                float b1 = (c0 + 1 < Nreal) ? bias[c0 + 1] : 0.f;
                float wr0 = xsrc ? Wrow[c0] : 0.f;
                float wr1 = xsrc ? Wrow[c0 + 1] : 0.f;
                if (r0 < M) {
                    float v0 = fmaxf(acc[i][j][0] + b0 + t0 * wr0, 0.f);
                    float v1 = fmaxf(acc[i][j][1] + b1 + t0 * wr1, 0.f);
                    uint32_t lo;
                    uint32_t hi = pack_hi(v0, v1, lo);
                    *reinterpret_cast<uint32_t*>(Ch + (size_t)r0 * Nstore + c0) = hi;
                    *reinterpret_cast<uint32_t*>(Cl + (size_t)r0 * Nstore + c0) = lo;
                }
                if (r0 + 8 < M) {
                    float v0 = fmaxf(acc[i][j][2] + b0 + t1 * wr0, 0.f);
                    float v1 = fmaxf(acc[i][j][3] + b1 + t1 * wr1, 0.f);
                    uint32_t lo;
                    uint32_t hi = pack_hi(v0, v1, lo);
                    *reinterpret_cast<uint32_t*>(Ch + (size_t)(r0 + 8) * Nstore + c0) = hi;
                    *reinterpret_cast<uint32_t*>(Cl + (size_t)(r0 + 8) * Nstore + c0) = lo;
                }
            }
        }
    }
}

// ===================== sigmoid ==============================================
__global__ void sigmoid_kernel(const float* __restrict__ logit,
                               const float* __restrict__ bp2,
                               float* __restrict__ out) {
    int i = blockIdx.x * blockDim.x + threadIdx.x;
    if (i >= N_EDGES) return;
    out[i] = 1.f / (1.f + expf(-(logit[i] + bp2[0])));
}

// ===================== host =================================================
static inline void launch_split(const float* W, int K, int NW, int Kpad,
                                int Npad, int perm, int off) {
    __nv_bfloat16 *wh, *wl;
    cudaGetSymbolAddress((void**)&wh, g_wt_hi);
    cudaGetSymbolAddress((void**)&wl, g_wt_lo);
    int tot = Npad * Kpad;
    split_weight_kernel<<<(tot + 255) / 256, 256>>>(W, K, NW, Kpad, Npad, perm,
                                                    wh + off, wl + off);
}

extern "C" void kernel_launch(void* const* d_in, const int* in_sizes, int n_in,
                              void* d_out, int out_size) {
    const float* x     = (const float*)d_in[0];
    const void*  eidx  = d_in[1];
    const float* trust = (const float*)d_in[2];
    const float* eq    = (const float*)d_in[3];
    const float* Wm1_1 = (const float*)d_in[4];
    const float* bm1_1 = (const float*)d_in[5];
    const float* Wm2_1 = (const float*)d_in[6];
    const float* bm2_1 = (const float*)d_in[7];
    const float* Wl_1  = (const float*)d_in[8];
    const float* bl_1  = (const float*)d_in[9];
    const float* Wm1_2 = (const float*)d_in[10];
    const float* bm1_2 = (const float*)d_in[11];
    const float* Wm2_2 = (const float*)d_in[12];
    const float* bm2_2 = (const float*)d_in[13];
    const float* Wl_2  = (const float*)d_in[14];
    const float* bl_2  = (const float*)d_in[15];
    const float* Wp1   = (const float*)d_in[16];
    const float* bp1   = (const float*)d_in[17];
    const float* Wp2   = (const float*)d_in[18];
    const float* bp2   = (const float*)d_in[19];
    float* out = (float*)d_out;

    float *aggr, *h1, *logit, *ex1, *ex2;
    cudaGetSymbolAddress((void**)&aggr,  g_aggr);
    cudaGetSymbolAddress((void**)&h1,    g_h1);
    cudaGetSymbolAddress((void**)&logit, g_logit);
    cudaGetSymbolAddress((void**)&ex1,   g_ex1);
    cudaGetSymbolAddress((void**)&ex2,   g_ex2);
    __nv_bfloat16 *wh, *wl, *eah, *eal, *hidh, *hidl, *h2h, *h2l;
    cudaGetSymbolAddress((void**)&wh,   g_wt_hi);
    cudaGetSymbolAddress((void**)&wl,   g_wt_lo);
    cudaGetSymbolAddress((void**)&eah,  g_ea_hi);
    cudaGetSymbolAddress((void**)&eal,  g_ea_lo);
    cudaGetSymbolAddress((void**)&hidh, g_hid_hi);
    cudaGetSymbolAddress((void**)&hidl, g_hid_lo);
    cudaGetSymbolAddress((void**)&h2h,  g_h2_hi);
    cudaGetSymbolAddress((void**)&h2l,  g_h2_lo);

    cudaFuncSetAttribute(gemm_pipe<3,3,1>, cudaFuncAttributeMaxDynamicSharedMemorySize, SMEM_BYTES);
    cudaFuncSetAttribute(gemm_pipe<3,1,0>, cudaFuncAttributeMaxDynamicSharedMemorySize, SMEM_BYTES);
    cudaFuncSetAttribute(gemm_pipe<0,0,0>, cudaFuncAttributeMaxDynamicSharedMemorySize, SMEM_BYTES);
    cudaFuncSetAttribute(gemm_pipe<0,3,0>, cudaFuncAttributeMaxDynamicSharedMemorySize, SMEM_BYTES);
    cudaFuncSetAttribute(gemm_pipe<5,2,0>, cudaFuncAttributeMaxDynamicSharedMemorySize, SMEM_BYTES);

    detect_idx_kernel<<<1, 32>>>(eidx);
    convert_idx_kernel<<<(2 * N_EDGES + 255) / 256, 256>>>(eidx);
    {
        long long tot = (long long)N_EDGES * 32;
        split_ea_kernel<<<(unsigned)((tot + 255) / 256), 256>>>(eq);
    }

    launch_split(Wm1_1, 129, 258, 128, 256, 1, OFF_Wm1_1);
    launch_split(Wm2_1, 256, 128, 256, 128, 0, OFF_Wm2_1);
    launch_split(Wl_1,  128, 256, 128, 256, 0, OFF_Wl_1);
    launch_split(Wm1_2, 129, 258, 128, 256, 1, OFF_Wm1_2);
    launch_split(Wm2_2, 256, 256, 256, 256, 0, OFF_Wm2_2);
    launch_split(Wl_2,  256, 128, 256, 128, 0, OFF_Wl_2);
    launch_split(Wp1,   384, 256, 384, 256, 0, OFF_Wp1);

    const int MB_E = N_EDGES / 128;               // 6250
    const int MB_N = (N_NODES + 127) / 128;       // 391

    // ---- layer 1 ----
    gemm_pipe<3,3,1><<<dim3(2, MB_E), 256, SMEM_BYTES>>>(
        N_EDGES, 256, 256, 128, 128, nullptr, eah, eal,
        wh + OFF_Wm1_1, wl + OFF_Wm1_1, bm1_1, nullptr, hidh, hidl,
        trust, nullptr, Wm1_1, ex1, 1);
    zero_kernel<<<(N_NODES * 128 + 255) / 256, 256>>>(aggr, (size_t)N_NODES * 128);
    gemm_pipe<3,1,0><<<dim3(1, MB_E), 256, SMEM_BYTES>>>(
        N_EDGES, 128, 128, 256, 256, nullptr, hidh, hidl,
        wh + OFF_Wm2_1, wl + OFF_Wm2_1, bm2_1, aggr, nullptr, nullptr,
        x, nullptr, Wm2_1, ex1, 0);
    gemm_pipe<0,0,0><<<dim3(2, MB_N), 256, SMEM_BYTES>>>(
        N_NODES, 256, 256, 128, 128, aggr, nullptr, nullptr,
        wh + OFF_Wl_1, wl + OFF_Wl_1, bl_1, h1, nullptr, nullptr,
        nullptr, nullptr, nullptr, nullptr, 1);

    // ---- layer 2 ----
    gemm_pipe<3,3,1><<<dim3(2, MB_E), 256, SMEM_BYTES>>>(
        N_EDGES, 256, 256, 128, 128, nullptr, eah, eal,
        wh + OFF_Wm1_2, wl + OFF_Wm1_2, bm1_2, nullptr, hidh, hidl,
        trust, nullptr, Wm1_2, ex2, 1);
    zero_kernel<<<(N_NODES * 256 + 255) / 256, 256>>>(aggr, (size_t)N_NODES * 256);
    gemm_pipe<3,1,0><<<dim3(2, MB_E), 256, SMEM_BYTES>>>(
        N_EDGES, 256, 256, 256, 256, nullptr, hidh, hidl,
        wh + OFF_Wm2_2, wl + OFF_Wm2_2, bm2_2, aggr, nullptr, nullptr,
        h1, nullptr, Wm2_2, ex2, 0);
    gemm_pipe<0,3,0><<<dim3(1, MB_N), 256, SMEM_BYTES>>>(
        N_NODES, 128, 128, 256, 256, aggr, nullptr, nullptr,
        wh + OFF_Wl_2, wl + OFF_Wl_2, bl_2, nullptr, h2h, h2l,
        nullptr, nullptr, nullptr, nullptr, 1);

    // ---- predictor ----
    zero_kernel<<<(N_EDGES + 255) / 256, 256>>>(logit, (size_t)N_EDGES);
    gemm_pipe<5,2,0><<<dim3(2, MB_E), 256, SMEM_BYTES>>>(
        N_EDGES, 256, 256, 384, 0, nullptr, nullptr, nullptr,
        wh + OFF_Wp1, wl + OFF_Wp1, bp1, logit, nullptr, nullptr,
        nullptr, Wp2, nullptr, nullptr, 0);
    sigmoid_kernel<<<(N_EDGES + 255) / 256, 256>>>(logit, bp2, out);
}

// round 16
// speedup vs baseline: 5.3688x; 1.1057x over previous
#include <cuda_runtime.h>
#include <cuda_bf16.h>
#include <cstdint>
#include <cstddef>

#define N_NODES 50000
#define N_EDGES 800000

// ===================== scratch ==============================================
__device__ __align__(16) __nv_bfloat16 g_ea_hi [(size_t)N_EDGES * 128];  // eq split
__device__ __align__(16) __nv_bfloat16 g_ea_lo [(size_t)N_EDGES * 128];
__device__ __align__(16) __nv_bfloat16 g_hid_hi[(size_t)N_EDGES * 256];
__device__ __align__(16) __nv_bfloat16 g_hid_lo[(size_t)N_EDGES * 256];
__device__ __align__(16) __nv_bfloat16 g_h2_hi [(size_t)N_NODES * 128];
__device__ __align__(16) __nv_bfloat16 g_h2_lo [(size_t)N_NODES * 128];
__device__ float g_ex1 [(size_t)N_EDGES * 2];
__device__ float g_ex2 [(size_t)N_EDGES * 2];
__device__ float g_aggr[(size_t)N_NODES * 256];
__device__ float g_h1  [(size_t)N_NODES * 256];
__device__ float g_u   [(size_t)N_NODES * 256];   // h2·Wp1[0:128] + bp1
__device__ float g_v   [(size_t)N_NODES * 256];   // h2·Wp1[128:256]
__device__ float g_zerobias[256];                 // zero-initialized
__device__ float g_logit[N_EDGES];
__device__ int   g_row[N_EDGES];
__device__ int   g_col[N_EDGES];
__device__ int   g_idx_is64;

#define WT_TOTAL 327680
__device__ __align__(16) __nv_bfloat16 g_wt_hi[WT_TOTAL];
__device__ __align__(16) __nv_bfloat16 g_wt_lo[WT_TOTAL];
#define OFF_Wm1_1 0        // 256 x 128
#define OFF_Wm2_1 32768    // 128 x 256
#define OFF_Wl_1  65536    // 256 x 128
#define OFF_Wm1_2 98304    // 256 x 128
#define OFF_Wm2_2 131072   // 256 x 256
#define OFF_Wl_2  196608   // 128 x 256
#define OFF_Wp1a  229376   // 256 x 128 (Wp1 rows 0..127)
#define OFF_Wp1b  262144   // 256 x 128 (rows 128..255)
#define OFF_Wp1e  294912   // 256 x 128 (rows 256..383)

// ===================== small helpers ========================================
__device__ __forceinline__ uint32_t smem_u32(const void* p) {
    uint32_t a;
    asm("{ .reg .u64 t; cvta.to.shared.u64 t, %1; cvt.u32.u64 %0, t; }"
        : "=r"(a) : "l"(p));
    return a;
}
__device__ __forceinline__ void cp_async16(uint32_t dst, const void* src) {
    asm volatile("cp.async.cg.shared.global [%0], [%1], 16;"
                 :: "r"(dst), "l"(src));
}
#define CP_COMMIT()  asm volatile("cp.async.commit_group;" ::: "memory")
#define CP_WAIT(n)   asm volatile("cp.async.wait_group %0;" :: "n"(n) : "memory")

__device__ __forceinline__ void mma16816(float* c, const uint32_t* a,
                                         const uint32_t* b) {
    asm volatile(
        "mma.sync.aligned.m16n8k16.row.col.f32.bf16.bf16.f32 "
        "{%0,%1,%2,%3}, {%4,%5,%6,%7}, {%8,%9}, {%0,%1,%2,%3};"
        : "+f"(c[0]), "+f"(c[1]), "+f"(c[2]), "+f"(c[3])
        : "r"(a[0]), "r"(a[1]), "r"(a[2]), "r"(a[3]), "r"(b[0]), "r"(b[1]));
}
__device__ __forceinline__ uint32_t pack_hi(float v0, float v1,
                                            uint32_t& lo_out) {
    __nv_bfloat16 h0 = __float2bfloat16_rn(v0);
    __nv_bfloat16 h1 = __float2bfloat16_rn(v1);
    __nv_bfloat16 l0 = __float2bfloat16_rn(v0 - __bfloat162float(h0));
    __nv_bfloat16 l1 = __float2bfloat16_rn(v1 - __bfloat162float(h1));
    lo_out = (uint32_t)__bfloat16_as_ushort(l0) |
             ((uint32_t)__bfloat16_as_ushort(l1) << 16);
    return (uint32_t)__bfloat16_as_ushort(h0) |
           ((uint32_t)__bfloat16_as_ushort(h1) << 16);
}
__device__ __forceinline__ float2 unsplit2(uint32_t h, uint32_t l) {
    float a0 = __bfloat162float(__ushort_as_bfloat16((unsigned short)(h & 0xffff))) +
               __bfloat162float(__ushort_as_bfloat16((unsigned short)(l & 0xffff)));
    float a1 = __bfloat162float(__ushort_as_bfloat16((unsigned short)(h >> 16))) +
               __bfloat162float(__ushort_as_bfloat16((unsigned short)(l >> 16)));
    return make_float2(a0, a1);
}

// ===================== index sniff / convert ================================
__global__ void detect_idx_kernel(const void* p) {
    if (blockIdx.x == 0 && threadIdx.x == 0) {
        const long long* q = (const long long*)p;
        int ok = 1;
        for (int i = 0; i < 256; i++) {
            long long v = q[i];
            if (v < 0 || v >= N_NODES) { ok = 0; break; }
        }
        g_idx_is64 = ok;
    }
}
__global__ void convert_idx_kernel(const void* p) {
    int i = blockIdx.x * blockDim.x + threadIdx.x;
    if (i >= 2 * N_EDGES) return;
    long long v;
    if (g_idx_is64) v = ((const long long*)p)[i];
    else            v = (long long)((const int*)p)[i];
    if (i < N_EDGES) g_row[i] = (int)v;
    else             g_col[i - N_EDGES] = (int)v;
}

__global__ void zero_kernel(float* __restrict__ p, size_t n) {
    size_t i = (size_t)blockIdx.x * blockDim.x + threadIdx.x;
    if (i < n) p[i] = 0.f;
}

// ===================== pre-split eq =========================================
__global__ void split_ea_kernel(const float* __restrict__ eq) {
    long long idx = (long long)blockIdx.x * blockDim.x + threadIdx.x;
    if (idx >= (long long)N_EDGES * 32) return;
    int e  = (int)(idx / 32);
    int k4 = (int)(idx % 32);
    float4 t = *reinterpret_cast<const float4*>(eq + (size_t)e * 128 + k4 * 4);
    uint32_t l01, l23;
    uint32_t h01 = pack_hi(t.x, t.y, l01);
    uint32_t h23 = pack_hi(t.z, t.w, l23);
    size_t o = (size_t)e * 128 + k4 * 4;
    *reinterpret_cast<uint2*>(g_ea_hi + o) = make_uint2(h01, h23);
    *reinterpret_cast<uint2*>(g_ea_lo + o) = make_uint2(l01, l23);
}

// ===================== weight split (row offset) ============================
__global__ void split_weight_kernel(const float* __restrict__ W, int K, int NW,
                                    int Kpad, int Npad, int rowOff,
                                    __nv_bfloat16* __restrict__ oh,
                                    __nv_bfloat16* __restrict__ ol) {
    int idx = blockIdx.x * blockDim.x + threadIdx.x;
    if (idx >= Npad * Kpad) return;
    int n = idx / Kpad, k = idx % Kpad;
    int sk = k + rowOff;
    float v = (sk < K) ? W[(size_t)sk * NW + n] : 0.f;
    __nv_bfloat16 hi = __float2bfloat16_rn(v);
    float lo = v - __bfloat162float(hi);
    oh[idx] = hi;
    ol[idx] = __float2bfloat16_rn(lo);
}

// ===================== pipelined bf16x3 mma GEMM ============================
// AMODE: 0 fp32 A (+convert; uses rawA words 0..8191);
//        3 pre-split bf16 A (rawA unused -> EX may stage weights at rawA[0..255]).
// EPI:   0 fp32 store; 1 scatter-atomic (+xsrc[row], +rank2 ex·Wrow);
//        3 split-bf16 store (+rank1 trust·Wrow);
//        4 predictor: relu(acc + u[row] + v[col]) dot Wp2 -> atomicAdd logit
//          (u = xsrc, v = Wrow, weights = Wp2).
// EX=1 (AMODE 3 only): compute hidden cols 256/257 in fp32 (blockIdx.x==0).
#define SMEM_BYTES 114688

template<int AMODE, int EPI, int EX>
__global__ __launch_bounds__(256, 2)
void gemm_pipe(int M, int Nstore, int Nreal, int K, int strideA,
               const float* __restrict__ A,
               const __nv_bfloat16* __restrict__ Ah,
               const __nv_bfloat16* __restrict__ Al,
               const __nv_bfloat16* __restrict__ Wth,
               const __nv_bfloat16* __restrict__ Wtl,
               const float* __restrict__ bias,
               float* __restrict__ Cout,
               __nv_bfloat16* __restrict__ Ch,
               __nv_bfloat16* __restrict__ Cl,
               const float* __restrict__ xsrc,
               const float* __restrict__ Wp2,
               const float* __restrict__ Wrow,
               float* __restrict__ ex,
               int act) {
    extern __shared__ char smem[];
    float*    rawA = reinterpret_cast<float*>(smem);
    uint32_t* AsH  = reinterpret_cast<uint32_t*>(smem + 32768);
    uint32_t* AsL  = reinterpret_cast<uint32_t*>(smem + 53248);
    uint32_t* BsH  = reinterpret_cast<uint32_t*>(smem + 73728);
    uint32_t* BsL  = reinterpret_cast<uint32_t*>(smem + 94208);
    const uint32_t sbRaw = smem_u32(rawA);
    const uint32_t sbAH  = smem_u32(AsH);
    const uint32_t sbAL  = smem_u32(AsL);
    const uint32_t sbBH  = smem_u32(BsH);
    const uint32_t sbBL  = smem_u32(BsL);

    const int tid = threadIdx.x;
    const int wid = tid >> 5, lane = tid & 31;
    const int warpM = (wid >> 2) * 64;
    const int warpN = (wid & 3) * 32;
    const int g = lane >> 2, q = lane & 3;
    const long long mBase = (long long)blockIdx.y * 128;
    const int nBase = blockIdx.x * 128;
    const int nChunks = K >> 5;

    float acc[4][4][4];
#pragma unroll
    for (int i = 0; i < 4; i++)
#pragma unroll
        for (int j = 0; j < 4; j++)
#pragma unroll
            for (int t = 0; t < 4; t++) acc[i][j][t] = 0.f;

    // EX staging: ONLY legal when AMODE != 0 (rawA otherwise unused).
    float exacc = 0.f;
    const bool doEX = EX && (blockIdx.x == 0);
    if (doEX) {
        rawA[tid] = Wrow[(size_t)((tid >> 1) + 1) * 258 + 256 + (tid & 1)];
    }

    auto issue_chunk = [&](int kc, int buf) {
        const int k0 = kc * 32;
        if (AMODE == 0) {
#pragma unroll
            for (int i = tid; i < 1024; i += 256) {
                int r = i >> 3, c4 = i & 7;
                long long gr = mBase + r;
                if (gr >= M) gr = 0;
                cp_async16(sbRaw + ((buf * 4096 + r * 32 + c4 * 4) << 2),
                           A + (size_t)gr * K + k0 + c4 * 4);
            }
        } else {
#pragma unroll
            for (int i = tid; i < 1024; i += 256) {
                int r = i >> 3, h = (i >> 2) & 1, c4 = i & 3;
                long long gr = mBase + r;
                if (gr >= M) gr = 0;      // OOB clamp (M may not divide by 128)
                size_t gi = (size_t)gr * strideA + k0 + c4 * 8;
                uint32_t dst = (h ? sbAL : sbAH) +
                               ((buf * 2560 + r * 20 + c4 * 4) << 2);
                cp_async16(dst, (h ? Al : Ah) + gi);
            }
        }
#pragma unroll
        for (int i = tid; i < 1024; i += 256) {
            int r = i >> 3, h = (i >> 2) & 1, c4 = i & 3;
            size_t gi = (size_t)(nBase + r) * K + k0 + c4 * 8;
            uint32_t dst = (h ? sbBL : sbBH) +
                           ((buf * 2560 + r * 20 + c4 * 4) << 2);
            cp_async16(dst, (h ? Wtl : Wth) + gi);
        }
        CP_COMMIT();
    };

    issue_chunk(0, 0);

    for (int kc = 0; kc < nChunks; kc++) {
        const int buf = kc & 1;
        __syncthreads();
        if (kc + 1 < nChunks) { issue_chunk(kc + 1, buf ^ 1); CP_WAIT(1); }
        else                  { CP_WAIT(0); }
        __syncthreads();

        if (AMODE == 0) {
#pragma unroll
            for (int i = tid; i < 2048; i += 256) {
                int r = i >> 4, kp = i & 15;
                long long gr = mBase + r;
                float2 v = *reinterpret_cast<float2*>(
                    rawA + buf * 4096 + r * 32 + kp * 2);
                float v0 = (gr < M) ? v.x : 0.f;
                float v1 = (gr < M) ? v.y : 0.f;
                uint32_t lo;
                uint32_t hi = pack_hi(v0, v1, lo);
                AsH[buf * 2560 + r * 20 + kp] = hi;
                AsL[buf * 2560 + r * 20 + kp] = lo;
            }
            __syncthreads();
        }

        const int ab = buf * 2560;

        // EX: fp32 accumulation of hidden cols 256/257 from the A smem tile
        if (doEX) {
            int r = tid >> 1, c = tid & 1;
            int base = ab + r * 20;
#pragma unroll
            for (int kp = 0; kp < 16; kp++) {
                float2 a = unsplit2(AsH[base + kp], AsL[base + kp]);
                int k = kc * 32 + kp * 2;
                exacc = fmaf(a.x, rawA[k * 2 + c], exacc);
                exacc = fmaf(a.y, rawA[(k + 1) * 2 + c], exacc);
            }
        }

#pragma unroll
        for (int s = 0; s < 2; s++) {
            uint32_t ah[4][4], al[4][4];
#pragma unroll
            for (int i = 0; i < 4; i++) {
                int base = ab + (warpM + i * 16 + g) * 20 + s * 8 + q;
                ah[i][0] = AsH[base];       ah[i][1] = AsH[base + 160];
                ah[i][2] = AsH[base + 4];   ah[i][3] = AsH[base + 164];
                al[i][0] = AsL[base];       al[i][1] = AsL[base + 160];
                al[i][2] = AsL[base + 4];   al[i][3] = AsL[base + 164];
            }
#pragma unroll
            for (int j = 0; j < 4; j++) {
                int bb = ab + (warpN + j * 8 + g) * 20 + s * 8 + q;
                uint32_t bh[2] = { BsH[bb], BsH[bb + 4] };
                uint32_t bl[2] = { BsL[bb], BsL[bb + 4] };
#pragma unroll
                for (int i = 0; i < 4; i++) {
                    mma16816(acc[i][j], ah[i], bh);
                    mma16816(acc[i][j], ah[i], bl);
                    mma16816(acc[i][j], al[i], bh);
                }
            }
        }
    }

    if (doEX) {
        int r = tid >> 1, c = tid & 1;
        long long e = mBase + r;
        float t = xsrc[e];
        ex[(size_t)e * 2 + c] =
            fmaxf(exacc + t * Wrow[256 + c] + bias[256 + c], 0.f);
    }

    // ===================== epilogues =====================
    if (EPI == 0) {
#pragma unroll
        for (int i = 0; i < 4; i++) {
            long long r0 = mBase + warpM + i * 16 + g;
#pragma unroll
            for (int j = 0; j < 4; j++) {
                int c0 = nBase + warpN + j * 8 + q * 2;
                if (c0 >= Nstore) continue;
                float b0 = (c0 < Nreal) ? bias[c0] : 0.f;
                float b1 = (c0 + 1 < Nreal) ? bias[c0 + 1] : 0.f;
                if (r0 < M) {
                    float v0 = acc[i][j][0] + b0, v1 = acc[i][j][1] + b1;
                    if (act) { v0 = fmaxf(v0, 0.f); v1 = fmaxf(v1, 0.f); }
                    *reinterpret_cast<float2*>(Cout + (size_t)r0 * Nstore + c0) =
                        make_float2(v0, v1);
                }
                if (r0 + 8 < M) {
                    float v0 = acc[i][j][2] + b0, v1 = acc[i][j][3] + b1;
                    if (act) { v0 = fmaxf(v0, 0.f); v1 = fmaxf(v1, 0.f); }
                    *reinterpret_cast<float2*>(Cout + (size_t)(r0 + 8) * Nstore + c0) =
                        make_float2(v0, v1);
                }
            }
        }
    } else if (EPI == 1) {
        const float* w256 = Wrow + (size_t)256 * Nstore;
        const float* w257 = Wrow + (size_t)257 * Nstore;
#pragma unroll
        for (int i = 0; i < 4; i++) {
            long long e0 = mBase + warpM + i * 16 + g;
            long long e1 = e0 + 8;
            int ra0 = g_row[e0], ca0 = g_col[e0];
            int ra1 = g_row[e1], ca1 = g_col[e1];
            float ea0 = ex[e0 * 2], eb0 = ex[e0 * 2 + 1];
            float ea1 = ex[e1 * 2], eb1 = ex[e1 * 2 + 1];
#pragma unroll
            for (int j = 0; j < 4; j++) {
                int c0 = nBase + warpN + j * 8 + q * 2;
                float b0 = bias[c0], b1 = bias[c0 + 1];
                float wa0 = w256[c0], wa1 = w256[c0 + 1];
                float wb0 = w257[c0], wb1 = w257[c0 + 1];
                float2 xv0 = *reinterpret_cast<const float2*>(
                    xsrc + (size_t)ra0 * Nstore + c0);
                float2 xv1 = *reinterpret_cast<const float2*>(
                    xsrc + (size_t)ra1 * Nstore + c0);
                atomicAdd(Cout + (size_t)ca0 * Nstore + c0,
                          acc[i][j][0] + b0 + xv0.x + ea0 * wa0 + eb0 * wb0);
                atomicAdd(Cout + (size_t)ca0 * Nstore + c0 + 1,
                          acc[i][j][1] + b1 + xv0.y + ea0 * wa1 + eb0 * wb1);
                atomicAdd(Cout + (size_t)ca1 * Nstore + c0,
                          acc[i][j][2] + b0 + xv1.x + ea1 * wa0 + eb1 * wb0);
                atomicAdd(Cout + (size_t)ca1 * Nstore + c0 + 1,
                          acc[i][j][3] + b1 + xv1.y + ea1 * wa1 + eb1 * wb1);
            }
        }
    } else if (EPI == 4) {
        // predictor: logit[e] += sum_c relu(acc + u[row][c] + v[col][c]) * Wp2[c]
        const float* u = xsrc;
        const float* v = Wrow;
#pragma unroll
        for (int i = 0; i < 4; i++) {
            long long e0 = mBase + warpM + i * 16 + g;
            long long e1 = e0 + 8;
            int ra0 = g_row[e0], ca0 = g_col[e0];
            int ra1 = g_row[e1], ca1 = g_col[e1];
            float p0 = 0.f, p1 = 0.f;
#pragma unroll
            for (int j = 0; j < 4; j++) {
                int c0 = nBase + warpN + j * 8 + q * 2;
                float w0 = Wp2[c0], w1 = Wp2[c0 + 1];
                float2 uu0 = *reinterpret_cast<const float2*>(u + (size_t)ra0 * 256 + c0);
                float2 vv0 = *reinterpret_cast<const float2*>(v + (size_t)ca0 * 256 + c0);
                float2 uu1 = *reinterpret_cast<const float2*>(u + (size_t)ra1 * 256 + c0);
                float2 vv1 = *reinterpret_cast<const float2*>(v + (size_t)ca1 * 256 + c0);
                p0 = fmaf(fmaxf(acc[i][j][0] + uu0.x + vv0.x, 0.f), w0, p0);
                p0 = fmaf(fmaxf(acc[i][j][1] + uu0.y + vv0.y, 0.f), w1, p0);
                p1 = fmaf(fmaxf(acc[i][j][2] + uu1.x + vv1.x, 0.f), w0, p1);
                p1 = fmaf(fmaxf(acc[i][j][3] + uu1.y + vv1.y, 0.f), w1, p1);
            }
            p0 += __shfl_xor_sync(0xffffffffu, p0, 1);
            p0 += __shfl_xor_sync(0xffffffffu, p0, 2);
            p1 += __shfl_xor_sync(0xffffffffu, p1, 1);
            p1 += __shfl_xor_sync(0xffffffffu, p1, 2);
            if (q == 0) {
                atomicAdd(Cout + e0, p0);
                atomicAdd(Cout + e1, p1);
            }
        }
    } else {
        // EPI 3: split bf16 store, bias + rank-1 trust term + relu
#pragma unroll
        for (int i = 0; i < 4; i++) {
            long long r0 = mBase + warpM + i * 16 + g;
            float t0 = 0.f, t1 = 0.f;
            if (xsrc) {
                if (r0 < M) t0 = xsrc[r0];
                if (r0 + 8 < M) t1 = xsrc[r0 + 8];
            }
#pragma unroll
            for (int j = 0; j < 4; j++) {
                int c0 = nBase + warpN + j * 8 + q * 2;
                if (c0 >= Nstore) continue;
                float b0 = (c0 < Nreal) ? bias[c0] : 0.f;
                float b1 = (c0 + 1 < Nreal) ? bias[c0 + 1] : 0.f;
                float wr0 = xsrc ? Wrow[c0] : 0.f;
                float wr1 = xsrc ? Wrow[c0 + 1] : 0.f;
                if (r0 < M) {
                    float v0 = fmaxf(acc[i][j][0] + b0 + t0 * wr0, 0.f);
                    float v1 = fmaxf(acc[i][j][1] + b1 + t0 * wr1, 0.f);
                    uint32_t lo;
                    uint32_t hi = pack_hi(v0, v1, lo);
                    *reinterpret_cast<uint32_t*>(Ch + (size_t)r0 * Nstore + c0) = hi;
                    *reinterpret_cast<uint32_t*>(Cl + (size_t)r0 * Nstore + c0) = lo;
                }
                if (r0 + 8 < M) {
                    float v0 = fmaxf(acc[i][j][2] + b0 + t1 * wr0, 0.f);
                    float v1 = fmaxf(acc[i][j][3] + b1 + t1 * wr1, 0.f);
                    uint32_t lo;
                    uint32_t hi = pack_hi(v0, v1, lo);
                    *reinterpret_cast<uint32_t*>(Ch + (size_t)(r0 + 8) * Nstore + c0) = hi;
                    *reinterpret_cast<uint32_t*>(Cl + (size_t)(r0 + 8) * Nstore + c0) = lo;
                }
            }
        }
    }
}

// ===================== sigmoid ==============================================
__global__ void sigmoid_kernel(const float* __restrict__ logit,
                               const float* __restrict__ bp2,
                               float* __restrict__ out) {
    int i = blockIdx.x * blockDim.x + threadIdx.x;
    if (i >= N_EDGES) return;
    out[i] = 1.f / (1.f + expf(-(logit[i] + bp2[0])));
}

// ===================== host =================================================
static inline void launch_split(const float* W, int K, int NW, int Kpad,
                                int Npad, int rowOff, int off) {
    __nv_bfloat16 *wh, *wl;
    cudaGetSymbolAddress((void**)&wh, g_wt_hi);
    cudaGetSymbolAddress((void**)&wl, g_wt_lo);
    int tot = Npad * Kpad;
    split_weight_kernel<<<(tot + 255) / 256, 256>>>(W, K, NW, Kpad, Npad, rowOff,
                                                    wh + off, wl + off);
}

extern "C" void kernel_launch(void* const* d_in, const int* in_sizes, int n_in,
                              void* d_out, int out_size) {
    const float* x     = (const float*)d_in[0];
    const void*  eidx  = d_in[1];
    const float* trust = (const float*)d_in[2];
    const float* eq    = (const float*)d_in[3];
    const float* Wm1_1 = (const float*)d_in[4];
    const float* bm1_1 = (const float*)d_in[5];
    const float* Wm2_1 = (const float*)d_in[6];
    const float* bm2_1 = (const float*)d_in[7];
    const float* Wl_1  = (const float*)d_in[8];
    const float* bl_1  = (const float*)d_in[9];
    const float* Wm1_2 = (const float*)d_in[10];
    const float* bm1_2 = (const float*)d_in[11];
    const float* Wm2_2 = (const float*)d_in[12];
    const float* bm2_2 = (const float*)d_in[13];
    const float* Wl_2  = (const float*)d_in[14];
    const float* bl_2  = (const float*)d_in[15];
    const float* Wp1   = (const float*)d_in[16];
    const float* bp1   = (const float*)d_in[17];
    const float* Wp2   = (const float*)d_in[18];
    const float* bp2   = (const float*)d_in[19];
    float* out = (float*)d_out;

    float *aggr, *h1, *logit, *ex1, *ex2, *u, *v, *zb;
    cudaGetSymbolAddress((void**)&aggr,  g_aggr);
    cudaGetSymbolAddress((void**)&h1,    g_h1);
    cudaGetSymbolAddress((void**)&logit, g_logit);
    cudaGetSymbolAddress((void**)&ex1,   g_ex1);
    cudaGetSymbolAddress((void**)&ex2,   g_ex2);
    cudaGetSymbolAddress((void**)&u,     g_u);
    cudaGetSymbolAddress((void**)&v,     g_v);
    cudaGetSymbolAddress((void**)&zb,    g_zerobias);
    __nv_bfloat16 *wh, *wl, *eah, *eal, *hidh, *hidl, *h2h, *h2l;
    cudaGetSymbolAddress((void**)&wh,   g_wt_hi);
    cudaGetSymbolAddress((void**)&wl,   g_wt_lo);
    cudaGetSymbolAddress((void**)&eah,  g_ea_hi);
    cudaGetSymbolAddress((void**)&eal,  g_ea_lo);
    cudaGetSymbolAddress((void**)&hidh, g_hid_hi);
    cudaGetSymbolAddress((void**)&hidl, g_hid_lo);
    cudaGetSymbolAddress((void**)&h2h,  g_h2_hi);
    cudaGetSymbolAddress((void**)&h2l,  g_h2_lo);

    cudaFuncSetAttribute(gemm_pipe<3,3,1>, cudaFuncAttributeMaxDynamicSharedMemorySize, SMEM_BYTES);
    cudaFuncSetAttribute(gemm_pipe<3,1,0>, cudaFuncAttributeMaxDynamicSharedMemorySize, SMEM_BYTES);
    cudaFuncSetAttribute(gemm_pipe<0,0,0>, cudaFuncAttributeMaxDynamicSharedMemorySize, SMEM_BYTES);
    cudaFuncSetAttribute(gemm_pipe<0,3,0>, cudaFuncAttributeMaxDynamicSharedMemorySize, SMEM_BYTES);
    cudaFuncSetAttribute(gemm_pipe<3,0,0>, cudaFuncAttributeMaxDynamicSharedMemorySize, SMEM_BYTES);
    cudaFuncSetAttribute(gemm_pipe<3,4,0>, cudaFuncAttributeMaxDynamicSharedMemorySize, SMEM_BYTES);

    detect_idx_kernel<<<1, 32>>>(eidx);
    convert_idx_kernel<<<(2 * N_EDGES + 255) / 256, 256>>>(eidx);
    {
        long long tot = (long long)N_EDGES * 32;
        split_ea_kernel<<<(unsigned)((tot + 255) / 256), 256>>>(eq);
    }

    launch_split(Wm1_1, 129, 258, 128, 256, 1,   OFF_Wm1_1);
    launch_split(Wm2_1, 256, 128, 256, 128, 0,   OFF_Wm2_1);
    launch_split(Wl_1,  128, 256, 128, 256, 0,   OFF_Wl_1);
    launch_split(Wm1_2, 129, 258, 128, 256, 1,   OFF_Wm1_2);
    launch_split(Wm2_2, 256, 256, 256, 256, 0,   OFF_Wm2_2);
    launch_split(Wl_2,  256, 128, 256, 128, 0,   OFF_Wl_2);
    launch_split(Wp1,   384, 256, 128, 256, 0,   OFF_Wp1a);
    launch_split(Wp1,   384, 256, 128, 256, 128, OFF_Wp1b);
    launch_split(Wp1,   384, 256, 128, 256, 256, OFF_Wp1e);

    const int MB_E = N_EDGES / 128;               // 6250
    const int MB_N = (N_NODES + 127) / 128;       // 391

    // ---- layer 1 ----
    gemm_pipe<3,3,1><<<dim3(2, MB_E), 256, SMEM_BYTES>>>(
        N_EDGES, 256, 256, 128, 128, nullptr, eah, eal,
        wh + OFF_Wm1_1, wl + OFF_Wm1_1, bm1_1, nullptr, hidh, hidl,
        trust, nullptr, Wm1_1, ex1, 1);
    zero_kernel<<<(N_NODES * 128 + 255) / 256, 256>>>(aggr, (size_t)N_NODES * 128);
    gemm_pipe<3,1,0><<<dim3(1, MB_E), 256, SMEM_BYTES>>>(
        N_EDGES, 128, 128, 256, 256, nullptr, hidh, hidl,
        wh + OFF_Wm2_1, wl + OFF_Wm2_1, bm2_1, aggr, nullptr, nullptr,
        x, nullptr, Wm2_1, ex1, 0);
    gemm_pipe<0,0,0><<<dim3(2, MB_N), 256, SMEM_BYTES>>>(
        N_NODES, 256, 256, 128, 128, aggr, nullptr, nullptr,
        wh + OFF_Wl_1, wl + OFF_Wl_1, bl_1, h1, nullptr, nullptr,
        nullptr, nullptr, nullptr, nullptr, 1);

    // ---- layer 2 ----
    gemm_pipe<3,3,1><<<dim3(2, MB_E), 256, SMEM_BYTES>>>(
        N_EDGES, 256, 256, 128, 128, nullptr, eah, eal,
        wh + OFF_Wm1_2, wl + OFF_Wm1_2, bm1_2, nullptr, hidh, hidl,
        trust, nullptr, Wm1_2, ex2, 1);
    zero_kernel<<<(N_NODES * 256 + 255) / 256, 256>>>(aggr, (size_t)N_NODES * 256);
    gemm_pipe<3,1,0><<<dim3(2, MB_E), 256, SMEM_BYTES>>>(
        N_EDGES, 256, 256, 256, 256, nullptr, hidh, hidl,
        wh + OFF_Wm2_2, wl + OFF_Wm2_2, bm2_2, aggr, nullptr, nullptr,
        h1, nullptr, Wm2_2, ex2, 0);
    gemm_pipe<0,3,0><<<dim3(1, MB_N), 256, SMEM_BYTES>>>(
        N_NODES, 128, 128, 256, 256, aggr, nullptr, nullptr,
        wh + OFF_Wl_2, wl + OFF_Wl_2, bl_2, nullptr, h2h, h2l,
        nullptr, nullptr, nullptr, nullptr, 1);

    // ---- predictor: node-factored u/v + edge eq GEMM with fused reduce ----
    gemm_pipe<3,0,0><<<dim3(2, MB_N), 256, SMEM_BYTES>>>(
        N_NODES, 256, 256, 128, 128, nullptr, h2h, h2l,
        wh + OFF_Wp1a, wl + OFF_Wp1a, bp1, u, nullptr, nullptr,
        nullptr, nullptr, nullptr, nullptr, 0);
    gemm_pipe<3,0,0><<<dim3(2, MB_N), 256, SMEM_BYTES>>>(
        N_NODES, 256, 256, 128, 128, nullptr, h2h, h2l,
        wh + OFF_Wp1b, wl + OFF_Wp1b, zb, v, nullptr, nullptr,
        nullptr, nullptr, nullptr, nullptr, 0);
    zero_kernel<<<(N_EDGES + 255) / 256, 256>>>(logit, (size_t)N_EDGES);
    gemm_pipe<3,4,0><<<dim3(2, MB_E), 256, SMEM_BYTES>>>(
        N_EDGES, 256, 256, 128, 128, nullptr, eah, eal,
        wh + OFF_Wp1e, wl + OFF_Wp1e, zb, logit, nullptr, nullptr,
        u, Wp2, v, nullptr, 0);
    sigmoid_kernel<<<(N_EDGES + 255) / 256, 256>>>(logit, bp2, out);
}